// round 1
// baseline (speedup 1.0000x reference)
#include <cuda_runtime.h>
#include <math.h>
#include <stdint.h>

// Problem constants
#define NN    50000
#define NE    1600000
#define INDIM 512
#define HD1   256
#define HD2R  129     // real cols of layer 2
#define HD2P  132     // padded stride (float4-aligned)

// ---------------- static scratch (no allocations allowed) ----------------
__device__ float d_HA[(size_t)NN * HD1];   // XW0 result; reused as H1W1 (stride HD2P)
__device__ float d_HB[(size_t)NN * HD1];   // softplus(agg1) result
__device__ int   d_col[NE];
__device__ float d_wgt[NE];
__device__ int   d_rp[NN + 1];
__device__ int   d_cur[NN];
__device__ int   d_cnt[NN];
__device__ float d_dinv[NN];
__device__ float d_W1p[HD1 * HD2P];

// ---------------- helpers ----------------
__device__ __forceinline__ float softplusf(float x) {
    // logaddexp(x, 0) — matches jax.nn.softplus (stable)
    return fmaxf(x, 0.0f) + log1pf(expf(-fabsf(x)));
}

// ---------------- CSR build ----------------
__global__ void k_zero_cnt() {
    int i = blockIdx.x * blockDim.x + threadIdx.x;
    if (i < NN) d_cnt[i] = 0;
}

__global__ void k_hist(const int* __restrict__ dst) {
    int e = blockIdx.x * blockDim.x + threadIdx.x;
    if (e < NE) atomicAdd(&d_cnt[dst[e]], 1);
}

__global__ void k_dinv() {
    int i = blockIdx.x * blockDim.x + threadIdx.x;
    if (i < NN) d_dinv[i] = rsqrtf((float)d_cnt[i] + 1.0f);  // +1 self-loop
}

// single-block exclusive scan of d_cnt -> d_rp, and copy into d_cur
__global__ void k_scan() {
    __shared__ int partial[1024];
    const int T = 1024;
    int t = threadIdx.x;
    const int chunk = (NN + T - 1) / T;
    int start = t * chunk;
    int end = start + chunk; if (end > NN) end = NN; if (start > NN) start = NN;
    int s = 0;
    for (int i = start; i < end; i++) s += d_cnt[i];
    partial[t] = s;
    __syncthreads();
    for (int off = 1; off < T; off <<= 1) {
        int v = partial[t];
        int add = (t >= off) ? partial[t - off] : 0;
        __syncthreads();
        partial[t] = v + add;
        __syncthreads();
    }
    int base = (t == 0) ? 0 : partial[t - 1];
    for (int i = start; i < end; i++) {
        d_rp[i] = base;
        d_cur[i] = base;
        base += d_cnt[i];
    }
    if (t == T - 1) d_rp[NN] = partial[T - 1];
}

__global__ void k_fill(const int* __restrict__ src, const int* __restrict__ dst) {
    int e = blockIdx.x * blockDim.x + threadIdx.x;
    if (e >= NE) return;
    int s = src[e], d = dst[e];
    int p = atomicAdd(&d_cur[d], 1);
    d_col[p] = s;
    d_wgt[p] = d_dinv[s] * d_dinv[d];
}

__global__ void k_padW1(const float* __restrict__ W1) {
    int i = blockIdx.x * blockDim.x + threadIdx.x;  // over HD1*HD2P
    if (i >= HD1 * HD2P) return;
    int k = i / HD2P, n = i % HD2P;
    d_W1p[i] = (n < HD2R) ? W1[k * HD2R + n] : 0.0f;
}

// ---------------- SGEMM 128x128x8, 256 threads, 8x8 micro ----------------
__global__ void __launch_bounds__(256, 2)
k_sgemm(const float* __restrict__ A, const float* __restrict__ B,
        float* __restrict__ C, int M, int N, int K, int lda, int ldb, int ldc) {
    __shared__ float As[8][128];
    __shared__ float Bs[8][128];
    int tid = threadIdx.x;
    int trow = tid >> 4;         // 0..15
    int tcol = tid & 15;         // 0..15
    int arow = tid >> 1;         // 0..127
    int acol = (tid & 1) * 4;    // 0 or 4
    int brow = tid >> 5;         // 0..7
    int bcol = (tid & 31) * 4;   // 0..124

    int gArow = blockIdx.y * 128 + arow;
    int gBcolBase = blockIdx.x * 128;

    float acc[8][8];
#pragma unroll
    for (int i = 0; i < 8; i++)
#pragma unroll
        for (int j = 0; j < 8; j++) acc[i][j] = 0.0f;

    for (int k0 = 0; k0 < K; k0 += 8) {
        float4 a4 = make_float4(0.f, 0.f, 0.f, 0.f);
        if (gArow < M)
            a4 = *(const float4*)(A + (size_t)gArow * lda + k0 + acol);
        As[acol + 0][arow] = a4.x;
        As[acol + 1][arow] = a4.y;
        As[acol + 2][arow] = a4.z;
        As[acol + 3][arow] = a4.w;

        float4 b4 = make_float4(0.f, 0.f, 0.f, 0.f);
        int gbcol = gBcolBase + bcol;
        if (gbcol < N)
            b4 = *(const float4*)(B + (size_t)(k0 + brow) * ldb + gbcol);
        *(float4*)&Bs[brow][bcol] = b4;
        __syncthreads();

#pragma unroll
        for (int kk = 0; kk < 8; kk++) {
            float4 a0 = *(float4*)&As[kk][trow * 8];
            float4 a1 = *(float4*)&As[kk][trow * 8 + 4];
            float4 b0 = *(float4*)&Bs[kk][tcol * 8];
            float4 b1 = *(float4*)&Bs[kk][tcol * 8 + 4];
            float ar[8] = {a0.x, a0.y, a0.z, a0.w, a1.x, a1.y, a1.z, a1.w};
            float br[8] = {b0.x, b0.y, b0.z, b0.w, b1.x, b1.y, b1.z, b1.w};
#pragma unroll
            for (int i = 0; i < 8; i++)
#pragma unroll
                for (int j = 0; j < 8; j++)
                    acc[i][j] = fmaf(ar[i], br[j], acc[i][j]);
        }
        __syncthreads();
    }

#pragma unroll
    for (int i = 0; i < 8; i++) {
        int grow = blockIdx.y * 128 + trow * 8 + i;
        if (grow >= M) continue;
        float* crow = C + (size_t)grow * ldc;
#pragma unroll
        for (int j4 = 0; j4 < 2; j4++) {
            int gcol = gBcolBase + tcol * 8 + j4 * 4;
            if (gcol < N) {
                float4 v = make_float4(acc[i][j4 * 4 + 0], acc[i][j4 * 4 + 1],
                                       acc[i][j4 * 4 + 2], acc[i][j4 * 4 + 3]);
                *(float4*)(crow + gcol) = v;
            }
        }
    }
}

// ---------------- aggregation layer 1: 64 threads/node, 256 cols ----------------
__global__ void __launch_bounds__(256)
k_agg1() {
    int node = blockIdx.x * 4 + (threadIdx.x >> 6);
    int lane = threadIdx.x & 63;
    const float* H = d_HA;
    float di = d_dinv[node];
    float sw = di * di;

    float4 v = *(const float4*)(H + (size_t)node * HD1 + lane * 4);
    float4 acc = make_float4(v.x * sw, v.y * sw, v.z * sw, v.w * sw);

    int e = d_rp[node], e1 = d_rp[node + 1];
    for (; e + 1 < e1; e += 2) {
        int s0 = d_col[e];     float w0 = d_wgt[e];
        int s1 = d_col[e + 1]; float w1 = d_wgt[e + 1];
        float4 v0 = *(const float4*)(H + (size_t)s0 * HD1 + lane * 4);
        float4 v1 = *(const float4*)(H + (size_t)s1 * HD1 + lane * 4);
        acc.x += v0.x * w0 + v1.x * w1;
        acc.y += v0.y * w0 + v1.y * w1;
        acc.z += v0.z * w0 + v1.z * w1;
        acc.w += v0.w * w0 + v1.w * w1;
    }
    if (e < e1) {
        int s0 = d_col[e]; float w0 = d_wgt[e];
        float4 v0 = *(const float4*)(H + (size_t)s0 * HD1 + lane * 4);
        acc.x += v0.x * w0; acc.y += v0.y * w0;
        acc.z += v0.z * w0; acc.w += v0.w * w0;
    }
    float4 o = make_float4(softplusf(acc.x), softplusf(acc.y),
                           softplusf(acc.z), softplusf(acc.w));
    *(float4*)(d_HB + (size_t)node * HD1 + lane * 4) = o;
}

// ---------------- aggregation layer 2 + epilogue: 32 threads/node ----------------
__global__ void __launch_bounds__(256)
k_agg2(float* __restrict__ out) {
    int node = blockIdx.x * 8 + (threadIdx.x >> 5);
    int lane = threadIdx.x & 31;
    const float* H = d_HA;  // reused, stride HD2P
    float di = d_dinv[node];
    float sw = di * di;

    const float* selfrow = H + (size_t)node * HD2P;
    float4 v = *(const float4*)(selfrow + lane * 4);
    float4 acc = make_float4(v.x * sw, v.y * sw, v.z * sw, v.w * sw);
    float acck = (lane == 0) ? selfrow[128] * sw : 0.0f;

    int e = d_rp[node], e1 = d_rp[node + 1];
    for (; e < e1; e++) {
        int s = d_col[e]; float w = d_wgt[e];
        const float* row = H + (size_t)s * HD2P;
        float4 v0 = *(const float4*)(row + lane * 4);
        acc.x += v0.x * w; acc.y += v0.y * w;
        acc.z += v0.z * w; acc.w += v0.w * w;
        if (lane == 0) acck += row[128] * w;
    }

    float4 lbd = make_float4(softplusf(acc.x), softplusf(acc.y),
                             softplusf(acc.z), softplusf(acc.w));
    float g = 0.0f, kap = 0.0f;
    if (lane == 0) {
        kap = softplusf(acck) + 0.1f;
        g = expf(lgammaf(1.0f + 1.0f / kap));
    }
    g = __shfl_sync(0xffffffffu, g, 0);

    const size_t ZOFF = 0;
    const size_t LOFF = (size_t)NN * 128;
    const size_t KOFF = (size_t)NN * 256;

    float4 z = make_float4(lbd.x * g, lbd.y * g, lbd.z * g, lbd.w * g);
    *(float4*)(out + ZOFF + (size_t)node * 128 + lane * 4) = z;
    *(float4*)(out + LOFF + (size_t)node * 128 + lane * 4) = lbd;
    if (lane == 0) out[KOFF + node] = kap;
}

// ---------------- launch ----------------
extern "C" void kernel_launch(void* const* d_in, const int* in_sizes, int n_in,
                              void* d_out, int out_size) {
    const float* x  = (const float*)d_in[0];
    const int* eidx = (const int*)d_in[1];
    const float* W0 = (const float*)d_in[2];
    const float* W1 = (const float*)d_in[3];
    float* out = (float*)d_out;

    const int* src = eidx;
    const int* dst = eidx + NE;

    float* HA; cudaGetSymbolAddress((void**)&HA, d_HA);
    float* HB; cudaGetSymbolAddress((void**)&HB, d_HB);
    float* W1p; cudaGetSymbolAddress((void**)&W1p, d_W1p);

    // CSR build
    k_zero_cnt<<<(NN + 255) / 256, 256>>>();
    k_hist<<<(NE + 255) / 256, 256>>>(dst);
    k_dinv<<<(NN + 255) / 256, 256>>>();
    k_scan<<<1, 1024>>>();
    k_fill<<<(NE + 255) / 256, 256>>>(src, dst);
    k_padW1<<<(HD1 * HD2P + 255) / 256, 256>>>(W1);

    // GEMM1: HA = x @ W0  (50000x256, K=512)
    {
        dim3 grid((HD1 + 127) / 128, (NN + 127) / 128);
        k_sgemm<<<grid, 256>>>(x, W0, HA, NN, HD1, INDIM, INDIM, HD1, HD1);
    }
    // AGG1 + softplus -> HB
    k_agg1<<<NN / 4, 256>>>();
    // GEMM2: HA(reused, stride 132) = HB @ W1p  (50000x132, K=256)
    {
        dim3 grid((HD2P + 127) / 128, (NN + 127) / 128);
        k_sgemm<<<grid, 256>>>(HB, W1p, HA, NN, HD2P, HD1, HD1, HD2P, HD2P);
    }
    // AGG2 + softplus + Weibull epilogue -> out
    k_agg2<<<NN / 8, 256>>>(out);
}

// round 2
// speedup vs baseline: 2.2205x; 2.2205x over previous
#include <cuda_runtime.h>
#include <math.h>
#include <stdint.h>

// Problem constants
#define NN    50000
#define NE    1600000
#define INDIM 512
#define HD1   256
#define HD2R  129     // real cols of layer 2
#define HD2P  132     // padded stride (float4-aligned)

#define SCAN_B 512
#define NBLK   ((NN + SCAN_B - 1) / SCAN_B)   // 98

// ---------------- static scratch (no allocations allowed) ----------------
__device__ float d_HA[(size_t)NN * HD1];   // XW0 result; reused as H1W1 (stride HD2P)
__device__ float d_HB[(size_t)NN * HD1];   // softplus(agg1) result
__device__ int   d_col[NE];
__device__ float d_wgt[NE];
__device__ int   d_rp[NN + 1];
__device__ int   d_cur[NN];
__device__ int   d_cnt[NN];
__device__ float d_dinv[NN];
__device__ float d_W1p[HD1 * HD2P];
__device__ int   d_bsum[NBLK];
__device__ int   d_boff[NBLK];

// ---------------- helpers ----------------
__device__ __forceinline__ float softplusf(float x) {
    return fmaxf(x, 0.0f) + log1pf(expf(-fabsf(x)));
}

__device__ __forceinline__ uint32_t f2tf32(float f) {
    uint32_t u;
    asm("cvt.rna.tf32.f32 %0, %1;" : "=r"(u) : "f"(f));
    return u;
}

__device__ __forceinline__ void mma_tf32(float c[4],
                                         uint32_t a0, uint32_t a1, uint32_t a2, uint32_t a3,
                                         uint32_t b0, uint32_t b1) {
    asm volatile(
        "mma.sync.aligned.m16n8k8.row.col.f32.tf32.tf32.f32 "
        "{%0,%1,%2,%3}, {%4,%5,%6,%7}, {%8,%9}, {%0,%1,%2,%3};\n"
        : "+f"(c[0]), "+f"(c[1]), "+f"(c[2]), "+f"(c[3])
        : "r"(a0), "r"(a1), "r"(a2), "r"(a3), "r"(b0), "r"(b1));
}

// ---------------- init: zero cnt + pad W1 ----------------
__global__ void k_init(const float* __restrict__ W1) {
    int i = blockIdx.x * blockDim.x + threadIdx.x;
    if (i < NN) d_cnt[i] = 0;
    if (i < HD1 * HD2P) {
        int k = i / HD2P, n = i % HD2P;
        d_W1p[i] = (n < HD2R) ? W1[k * HD2R + n] : 0.0f;
    }
}

__global__ void k_hist(const int* __restrict__ dst) {
    int e = blockIdx.x * blockDim.x + threadIdx.x;
    if (e < NE) atomicAdd(&d_cnt[dst[e]], 1);
}

// ---------------- parallel scan: block sums -> serial scan -> local scan ----------------
__global__ void k_blocksum() {
    __shared__ int sh[SCAN_B];
    int t = threadIdx.x;
    int i = blockIdx.x * SCAN_B + t;
    sh[t] = (i < NN) ? d_cnt[i] : 0;
    __syncthreads();
    for (int off = SCAN_B / 2; off > 0; off >>= 1) {
        if (t < off) sh[t] += sh[t + off];
        __syncthreads();
    }
    if (t == 0) d_bsum[blockIdx.x] = sh[0];
}

__global__ void k_bscan() {
    int run = 0;
    for (int b = 0; b < NBLK; b++) {
        d_boff[b] = run;
        run += d_bsum[b];
    }
}

__global__ void k_local() {
    __shared__ int sh[SCAN_B];
    int t = threadIdx.x;
    int i = blockIdx.x * SCAN_B + t;
    int v = (i < NN) ? d_cnt[i] : 0;
    sh[t] = v;
    __syncthreads();
    // Hillis-Steele inclusive scan
    for (int off = 1; off < SCAN_B; off <<= 1) {
        int add = (t >= off) ? sh[t - off] : 0;
        __syncthreads();
        sh[t] += add;
        __syncthreads();
    }
    if (i < NN) {
        int incl = sh[t];
        int base = d_boff[blockIdx.x] + incl - v;
        d_rp[i] = base;
        d_cur[i] = base;
        d_dinv[i] = rsqrtf((float)v + 1.0f);
        if (i == NN - 1) d_rp[NN] = d_boff[blockIdx.x] + incl;
    }
}

__global__ void k_fill(const int* __restrict__ src, const int* __restrict__ dst) {
    int e = blockIdx.x * blockDim.x + threadIdx.x;
    if (e >= NE) return;
    int s = src[e], d = dst[e];
    int p = atomicAdd(&d_cur[d], 1);
    d_col[p] = s;
    d_wgt[p] = d_dinv[s] * d_dinv[d];
}

// ---------------- TF32 tensor-core GEMM: 128x128 tile, BK=32, 256 threads ----------------
// A row-major MxK, B row-major KxN, C row-major MxN (fp32 in, tf32 mma, fp32 out)
__global__ void __launch_bounds__(256, 1)
k_gemm_tf32(const float* __restrict__ A, const float* __restrict__ B,
            float* __restrict__ C, int M, int N, int K,
            int lda, int ldb, int ldc) {
    __shared__ uint32_t As[128][36];   // [m][k], stride 36 -> conflict-free frags
    __shared__ uint32_t Bs[32][136];   // [k][n], stride 136 -> conflict-free frags

    const int tid = threadIdx.x;
    const int warp = tid >> 5;
    const int lane = tid & 31;
    const int wm = warp >> 2;      // 0..1 -> 64 rows each
    const int wn = warp & 3;       // 0..3 -> 32 cols each
    const int g = lane >> 2;       // 0..7
    const int t = lane & 3;        // 0..3

    const int bm = blockIdx.y * 128;
    const int bn = blockIdx.x * 128;

    float acc[4][4][4];
#pragma unroll
    for (int mt = 0; mt < 4; mt++)
#pragma unroll
        for (int nt = 0; nt < 4; nt++)
#pragma unroll
            for (int j = 0; j < 4; j++) acc[mt][nt][j] = 0.0f;

    const float4 z4 = make_float4(0.f, 0.f, 0.f, 0.f);
    float4 ra[4], rb[4];

    // load tile k0=0
#pragma unroll
    for (int i = 0; i < 4; i++) {
        int idx = tid + 256 * i;
        int r = idx >> 3, c = (idx & 7) << 2;
        int gr = bm + r;
        ra[i] = (gr < M) ? *(const float4*)(A + (size_t)gr * lda + c) : z4;
    }
#pragma unroll
    for (int i = 0; i < 4; i++) {
        int idx = tid + 256 * i;
        int kr = idx >> 5, c = (idx & 31) << 2;
        int gc = bn + c;
        rb[i] = (gc < N) ? *(const float4*)(B + (size_t)kr * ldb + gc) : z4;
    }
    // store tile 0 to smem (cvt to tf32)
#pragma unroll
    for (int i = 0; i < 4; i++) {
        int idx = tid + 256 * i;
        int r = idx >> 3, c = (idx & 7) << 2;
        uint4 u = make_uint4(f2tf32(ra[i].x), f2tf32(ra[i].y), f2tf32(ra[i].z), f2tf32(ra[i].w));
        *(uint4*)&As[r][c] = u;
    }
#pragma unroll
    for (int i = 0; i < 4; i++) {
        int idx = tid + 256 * i;
        int kr = idx >> 5, c = (idx & 31) << 2;
        uint4 u = make_uint4(f2tf32(rb[i].x), f2tf32(rb[i].y), f2tf32(rb[i].z), f2tf32(rb[i].w));
        *(uint4*)&Bs[kr][c] = u;
    }
    __syncthreads();

    const int nIter = K >> 5;
    for (int it = 0; it < nIter; it++) {
        // prefetch next tile into registers
        if (it + 1 < nIter) {
            int k0 = (it + 1) << 5;
#pragma unroll
            for (int i = 0; i < 4; i++) {
                int idx = tid + 256 * i;
                int r = idx >> 3, c = (idx & 7) << 2;
                int gr = bm + r;
                ra[i] = (gr < M) ? *(const float4*)(A + (size_t)gr * lda + k0 + c) : z4;
            }
#pragma unroll
            for (int i = 0; i < 4; i++) {
                int idx = tid + 256 * i;
                int kr = idx >> 5, c = (idx & 31) << 2;
                int gc = bn + c;
                rb[i] = (gc < N) ? *(const float4*)(B + (size_t)(k0 + kr) * ldb + gc) : z4;
            }
        }
        // compute on current smem tile
#pragma unroll
        for (int kt = 0; kt < 4; kt++) {
            const int kk = (kt << 3) + t;
            uint32_t af[4][4];
#pragma unroll
            for (int mt = 0; mt < 4; mt++) {
                int m = wm * 64 + mt * 16 + g;
                af[mt][0] = As[m][kk];
                af[mt][1] = As[m + 8][kk];
                af[mt][2] = As[m][kk + 4];
                af[mt][3] = As[m + 8][kk + 4];
            }
            uint32_t bf[4][2];
#pragma unroll
            for (int nt = 0; nt < 4; nt++) {
                int n = wn * 32 + nt * 8 + g;
                bf[nt][0] = Bs[kk][n];
                bf[nt][1] = Bs[kk + 4][n];
            }
#pragma unroll
            for (int mt = 0; mt < 4; mt++)
#pragma unroll
                for (int nt = 0; nt < 4; nt++)
                    mma_tf32(acc[mt][nt], af[mt][0], af[mt][1], af[mt][2], af[mt][3],
                             bf[nt][0], bf[nt][1]);
        }
        __syncthreads();
        if (it + 1 < nIter) {
#pragma unroll
            for (int i = 0; i < 4; i++) {
                int idx = tid + 256 * i;
                int r = idx >> 3, c = (idx & 7) << 2;
                uint4 u = make_uint4(f2tf32(ra[i].x), f2tf32(ra[i].y), f2tf32(ra[i].z), f2tf32(ra[i].w));
                *(uint4*)&As[r][c] = u;
            }
#pragma unroll
            for (int i = 0; i < 4; i++) {
                int idx = tid + 256 * i;
                int kr = idx >> 5, c = (idx & 31) << 2;
                uint4 u = make_uint4(f2tf32(rb[i].x), f2tf32(rb[i].y), f2tf32(rb[i].z), f2tf32(rb[i].w));
                *(uint4*)&Bs[kr][c] = u;
            }
            __syncthreads();
        }
    }

    // epilogue
#pragma unroll
    for (int mt = 0; mt < 4; mt++) {
        int r0 = bm + wm * 64 + mt * 16 + g;
        int r1 = r0 + 8;
#pragma unroll
        for (int nt = 0; nt < 4; nt++) {
            int c = bn + wn * 32 + nt * 8 + t * 2;
            if (c < N) {
                if (r0 < M) {
                    float2 v = make_float2(acc[mt][nt][0], acc[mt][nt][1]);
                    *(float2*)(C + (size_t)r0 * ldc + c) = v;
                }
                if (r1 < M) {
                    float2 v = make_float2(acc[mt][nt][2], acc[mt][nt][3]);
                    *(float2*)(C + (size_t)r1 * ldc + c) = v;
                }
            }
        }
    }
}

// ---------------- aggregation layer 1: 64 threads/node, 256 cols ----------------
__global__ void __launch_bounds__(256)
k_agg1() {
    int node = blockIdx.x * 4 + (threadIdx.x >> 6);
    int lane = threadIdx.x & 63;
    const float* H = d_HA;
    float di = d_dinv[node];
    float sw = di * di;

    float4 v = *(const float4*)(H + (size_t)node * HD1 + lane * 4);
    float4 acc = make_float4(v.x * sw, v.y * sw, v.z * sw, v.w * sw);

    int e = d_rp[node], e1 = d_rp[node + 1];
    for (; e + 3 < e1; e += 4) {
        int s0 = d_col[e];     float w0 = d_wgt[e];
        int s1 = d_col[e + 1]; float w1 = d_wgt[e + 1];
        int s2 = d_col[e + 2]; float w2 = d_wgt[e + 2];
        int s3 = d_col[e + 3]; float w3 = d_wgt[e + 3];
        float4 v0 = *(const float4*)(H + (size_t)s0 * HD1 + lane * 4);
        float4 v1 = *(const float4*)(H + (size_t)s1 * HD1 + lane * 4);
        float4 v2 = *(const float4*)(H + (size_t)s2 * HD1 + lane * 4);
        float4 v3 = *(const float4*)(H + (size_t)s3 * HD1 + lane * 4);
        acc.x += v0.x * w0 + v1.x * w1 + v2.x * w2 + v3.x * w3;
        acc.y += v0.y * w0 + v1.y * w1 + v2.y * w2 + v3.y * w3;
        acc.z += v0.z * w0 + v1.z * w1 + v2.z * w2 + v3.z * w3;
        acc.w += v0.w * w0 + v1.w * w1 + v2.w * w2 + v3.w * w3;
    }
    for (; e < e1; e++) {
        int s0 = d_col[e]; float w0 = d_wgt[e];
        float4 v0 = *(const float4*)(H + (size_t)s0 * HD1 + lane * 4);
        acc.x += v0.x * w0; acc.y += v0.y * w0;
        acc.z += v0.z * w0; acc.w += v0.w * w0;
    }
    float4 o = make_float4(softplusf(acc.x), softplusf(acc.y),
                           softplusf(acc.z), softplusf(acc.w));
    *(float4*)(d_HB + (size_t)node * HD1 + lane * 4) = o;
}

// ---------------- aggregation layer 2 + epilogue: 32 threads/node ----------------
__global__ void __launch_bounds__(256)
k_agg2(float* __restrict__ out) {
    int node = blockIdx.x * 8 + (threadIdx.x >> 5);
    int lane = threadIdx.x & 31;
    const float* H = d_HA;  // reused, stride HD2P
    float di = d_dinv[node];
    float sw = di * di;

    const float* selfrow = H + (size_t)node * HD2P;
    float4 v = *(const float4*)(selfrow + lane * 4);
    float4 acc = make_float4(v.x * sw, v.y * sw, v.z * sw, v.w * sw);
    float acck = (lane == 0) ? selfrow[128] * sw : 0.0f;

    int e = d_rp[node], e1 = d_rp[node + 1];
    for (; e + 1 < e1; e += 2) {
        int s0 = d_col[e];     float w0 = d_wgt[e];
        int s1 = d_col[e + 1]; float w1 = d_wgt[e + 1];
        const float* row0 = H + (size_t)s0 * HD2P;
        const float* row1 = H + (size_t)s1 * HD2P;
        float4 v0 = *(const float4*)(row0 + lane * 4);
        float4 v1 = *(const float4*)(row1 + lane * 4);
        acc.x += v0.x * w0 + v1.x * w1;
        acc.y += v0.y * w0 + v1.y * w1;
        acc.z += v0.z * w0 + v1.z * w1;
        acc.w += v0.w * w0 + v1.w * w1;
        if (lane == 0) acck += row0[128] * w0 + row1[128] * w1;
    }
    if (e < e1) {
        int s = d_col[e]; float w = d_wgt[e];
        const float* row = H + (size_t)s * HD2P;
        float4 v0 = *(const float4*)(row + lane * 4);
        acc.x += v0.x * w; acc.y += v0.y * w;
        acc.z += v0.z * w; acc.w += v0.w * w;
        if (lane == 0) acck += row[128] * w;
    }

    float4 lbd = make_float4(softplusf(acc.x), softplusf(acc.y),
                             softplusf(acc.z), softplusf(acc.w));
    float g = 0.0f, kap = 0.0f;
    if (lane == 0) {
        kap = softplusf(acck) + 0.1f;
        g = expf(lgammaf(1.0f + 1.0f / kap));
    }
    g = __shfl_sync(0xffffffffu, g, 0);

    const size_t ZOFF = 0;
    const size_t LOFF = (size_t)NN * 128;
    const size_t KOFF = (size_t)NN * 256;

    float4 z = make_float4(lbd.x * g, lbd.y * g, lbd.z * g, lbd.w * g);
    *(float4*)(out + ZOFF + (size_t)node * 128 + lane * 4) = z;
    *(float4*)(out + LOFF + (size_t)node * 128 + lane * 4) = lbd;
    if (lane == 0) out[KOFF + node] = kap;
}

// ---------------- launch ----------------
extern "C" void kernel_launch(void* const* d_in, const int* in_sizes, int n_in,
                              void* d_out, int out_size) {
    const float* x  = (const float*)d_in[0];
    const int* eidx = (const int*)d_in[1];
    const float* W0 = (const float*)d_in[2];
    const float* W1 = (const float*)d_in[3];
    float* out = (float*)d_out;

    const int* src = eidx;
    const int* dst = eidx + NE;

    float* HA; cudaGetSymbolAddress((void**)&HA, d_HA);
    float* HB; cudaGetSymbolAddress((void**)&HB, d_HB);
    float* W1p; cudaGetSymbolAddress((void**)&W1p, d_W1p);

    // CSR build
    k_init<<<(NN + 255) / 256, 256>>>(W1);
    k_hist<<<(NE + 255) / 256, 256>>>(dst);
    k_blocksum<<<NBLK, SCAN_B>>>();
    k_bscan<<<1, 1>>>();
    k_local<<<NBLK, SCAN_B>>>();
    k_fill<<<(NE + 255) / 256, 256>>>(src, dst);

    // GEMM1: HA = x @ W0  (50000x256, K=512) — TF32 tensor cores
    {
        dim3 grid((HD1 + 127) / 128, (NN + 127) / 128);
        k_gemm_tf32<<<grid, 256>>>(x, W0, HA, NN, HD1, INDIM, INDIM, HD1, HD1);
    }
    // AGG1 + softplus -> HB
    k_agg1<<<NN / 4, 256>>>();
    // GEMM2: HA(reused, stride 132) = HB @ W1p  (50000x132, K=256)
    {
        dim3 grid((HD2P + 127) / 128, (NN + 127) / 128);
        k_gemm_tf32<<<grid, 256>>>(HB, W1p, HA, NN, HD2P, HD1, HD1, HD2P, HD2P);
    }
    // AGG2 + softplus + Weibull epilogue -> out
    k_agg2<<<NN / 8, 256>>>(out);
}

// round 5
// speedup vs baseline: 2.4117x; 1.0861x over previous
#include <cuda_runtime.h>
#include <cuda_fp16.h>
#include <math.h>
#include <stdint.h>

// Problem constants
#define NN    50000
#define NE    1600000
#define INDIM 512
#define HD1   256
#define HD2R  129     // real cols of layer 2
#define HD2P  136     // padded stride in halves (272B, 16B-aligned)

#define SCAN_B 512
#define NBLK   ((NN + SCAN_B - 1) / SCAN_B)   // 98

// init kernel must cover BOTH d_cnt[NN] and d_W1p[HD1*HD2P]
#define INIT_N ((NN) > (HD1 * HD2P) ? (NN) : (HD1 * HD2P))

// ---------------- static scratch (no allocations allowed) ----------------
__device__ __half d_HAh[(size_t)NN * HD1];  // fp16 XW0; reused as fp16 H1W1 (stride HD2P)
__device__ float  d_HB[(size_t)NN * HD1];   // fp32 softplus(agg1)
__device__ int    d_col[NE];
__device__ int    d_rp[NN + 1];
__device__ int    d_cur[NN];
__device__ int    d_cnt[NN];
__device__ float  d_dinv[NN];
__device__ float  d_W1p[HD1 * HD2P];
__device__ int    d_bsum[NBLK];
__device__ int    d_boff[NBLK];

// ---------------- helpers ----------------
__device__ __forceinline__ float softplusf(float x) {
    return fmaxf(x, 0.0f) + log1pf(expf(-fabsf(x)));
}

__device__ __forceinline__ uint32_t f2tf32(float f) {
    uint32_t u;
    asm("cvt.rna.tf32.f32 %0, %1;" : "=r"(u) : "f"(f));
    return u;
}

__device__ __forceinline__ void mma_tf32(float c[4],
                                         uint32_t a0, uint32_t a1, uint32_t a2, uint32_t a3,
                                         uint32_t b0, uint32_t b1) {
    asm volatile(
        "mma.sync.aligned.m16n8k8.row.col.f32.tf32.tf32.f32 "
        "{%0,%1,%2,%3}, {%4,%5,%6,%7}, {%8,%9}, {%0,%1,%2,%3};\n"
        : "+f"(c[0]), "+f"(c[1]), "+f"(c[2]), "+f"(c[3])
        : "r"(a0), "r"(a1), "r"(a2), "r"(a3), "r"(b0), "r"(b1));
}

// ---------------- init: zero cnt + pad W1 (grid covers INIT_N) ----------------
__global__ void k_init(const float* __restrict__ W1) {
    int i = blockIdx.x * blockDim.x + threadIdx.x;
    if (i < NN) d_cnt[i] = 0;
    if (i < HD1 * HD2P) {
        int k = i / HD2P, n = i % HD2P;
        d_W1p[i] = (n < HD2R) ? W1[k * HD2R + n] : 0.0f;
    }
}

__global__ void k_hist(const int* __restrict__ dst) {
    int e = blockIdx.x * blockDim.x + threadIdx.x;
    if (e < NE) atomicAdd(&d_cnt[dst[e]], 1);
}

// ---------------- parallel scan: block sums -> 1-block scan -> local scan ----------------
__global__ void k_blocksum() {
    __shared__ int sh[SCAN_B];
    int t = threadIdx.x;
    int i = blockIdx.x * SCAN_B + t;
    sh[t] = (i < NN) ? d_cnt[i] : 0;
    __syncthreads();
    for (int off = SCAN_B / 2; off > 0; off >>= 1) {
        if (t < off) sh[t] += sh[t + off];
        __syncthreads();
    }
    if (t == 0) d_bsum[blockIdx.x] = sh[0];
}

__global__ void k_bscan() {
    __shared__ int sh[128];
    int t = threadIdx.x;
    int v = (t < NBLK) ? d_bsum[t] : 0;
    sh[t] = v;
    __syncthreads();
    for (int off = 1; off < 128; off <<= 1) {
        int add = (t >= off) ? sh[t - off] : 0;
        __syncthreads();
        sh[t] += add;
        __syncthreads();
    }
    if (t < NBLK) d_boff[t] = sh[t] - v;   // exclusive
}

__global__ void k_local() {
    __shared__ int sh[SCAN_B];
    int t = threadIdx.x;
    int i = blockIdx.x * SCAN_B + t;
    int v = (i < NN) ? d_cnt[i] : 0;
    sh[t] = v;
    __syncthreads();
    for (int off = 1; off < SCAN_B; off <<= 1) {
        int add = (t >= off) ? sh[t - off] : 0;
        __syncthreads();
        sh[t] += add;
        __syncthreads();
    }
    if (i < NN) {
        int incl = sh[t];
        int base = d_boff[blockIdx.x] + incl - v;
        d_rp[i] = base;
        d_cur[i] = base;
        d_dinv[i] = rsqrtf((float)v + 1.0f);
        if (i == NN - 1) d_rp[NN] = d_boff[blockIdx.x] + incl;
    }
}

__global__ void k_fill(const int* __restrict__ src, const int* __restrict__ dst) {
    int e = blockIdx.x * blockDim.x + threadIdx.x;
    if (e >= NE) return;
    int s = src[e], d = dst[e];
    int p = atomicAdd(&d_cur[d], 1);
    d_col[p] = s;
}

// ---------------- TF32 tensor-core GEMM: 128x128 tile, BK=32, 256 threads ----------------
// A row-major MxK fp32, B row-major KxN fp32; C = half (OUT_HALF) or float
template <bool OUT_HALF>
__global__ void __launch_bounds__(256, 1)
k_gemm_tf32(const float* __restrict__ A, const float* __restrict__ B,
            void* __restrict__ Cv, int M, int N, int K,
            int lda, int ldb, int ldc) {
    __shared__ uint32_t As[128][36];
    __shared__ uint32_t Bs[32][136];

    const int tid = threadIdx.x;
    const int warp = tid >> 5;
    const int lane = tid & 31;
    const int wm = warp >> 2;
    const int wn = warp & 3;
    const int g = lane >> 2;
    const int t = lane & 3;

    const int bm = blockIdx.y * 128;
    const int bn = blockIdx.x * 128;

    float acc[4][4][4];
#pragma unroll
    for (int mt = 0; mt < 4; mt++)
#pragma unroll
        for (int nt = 0; nt < 4; nt++)
#pragma unroll
            for (int j = 0; j < 4; j++) acc[mt][nt][j] = 0.0f;

    const float4 z4 = make_float4(0.f, 0.f, 0.f, 0.f);
    float4 ra[4], rb[4];

#pragma unroll
    for (int i = 0; i < 4; i++) {
        int idx = tid + 256 * i;
        int r = idx >> 3, c = (idx & 7) << 2;
        int gr = bm + r;
        ra[i] = (gr < M) ? *(const float4*)(A + (size_t)gr * lda + c) : z4;
    }
#pragma unroll
    for (int i = 0; i < 4; i++) {
        int idx = tid + 256 * i;
        int kr = idx >> 5, c = (idx & 31) << 2;
        int gc = bn + c;
        rb[i] = (gc < N) ? *(const float4*)(B + (size_t)kr * ldb + gc) : z4;
    }
#pragma unroll
    for (int i = 0; i < 4; i++) {
        int idx = tid + 256 * i;
        int r = idx >> 3, c = (idx & 7) << 2;
        uint4 u = make_uint4(f2tf32(ra[i].x), f2tf32(ra[i].y), f2tf32(ra[i].z), f2tf32(ra[i].w));
        *(uint4*)&As[r][c] = u;
    }
#pragma unroll
    for (int i = 0; i < 4; i++) {
        int idx = tid + 256 * i;
        int kr = idx >> 5, c = (idx & 31) << 2;
        uint4 u = make_uint4(f2tf32(rb[i].x), f2tf32(rb[i].y), f2tf32(rb[i].z), f2tf32(rb[i].w));
        *(uint4*)&Bs[kr][c] = u;
    }
    __syncthreads();

    const int nIter = K >> 5;
    for (int it = 0; it < nIter; it++) {
        if (it + 1 < nIter) {
            int k0 = (it + 1) << 5;
#pragma unroll
            for (int i = 0; i < 4; i++) {
                int idx = tid + 256 * i;
                int r = idx >> 3, c = (idx & 7) << 2;
                int gr = bm + r;
                ra[i] = (gr < M) ? *(const float4*)(A + (size_t)gr * lda + k0 + c) : z4;
            }
#pragma unroll
            for (int i = 0; i < 4; i++) {
                int idx = tid + 256 * i;
                int kr = idx >> 5, c = (idx & 31) << 2;
                int gc = bn + c;
                rb[i] = (gc < N) ? *(const float4*)(B + (size_t)(k0 + kr) * ldb + gc) : z4;
            }
        }
#pragma unroll
        for (int kt = 0; kt < 4; kt++) {
            const int kk = (kt << 3) + t;
            uint32_t af[4][4];
#pragma unroll
            for (int mt = 0; mt < 4; mt++) {
                int m = wm * 64 + mt * 16 + g;
                af[mt][0] = As[m][kk];
                af[mt][1] = As[m + 8][kk];
                af[mt][2] = As[m][kk + 4];
                af[mt][3] = As[m + 8][kk + 4];
            }
            uint32_t bf[4][2];
#pragma unroll
            for (int nt = 0; nt < 4; nt++) {
                int n = wn * 32 + nt * 8 + g;
                bf[nt][0] = Bs[kk][n];
                bf[nt][1] = Bs[kk + 4][n];
            }
#pragma unroll
            for (int mt = 0; mt < 4; mt++)
#pragma unroll
                for (int nt = 0; nt < 4; nt++)
                    mma_tf32(acc[mt][nt], af[mt][0], af[mt][1], af[mt][2], af[mt][3],
                             bf[nt][0], bf[nt][1]);
        }
        __syncthreads();
        if (it + 1 < nIter) {
#pragma unroll
            for (int i = 0; i < 4; i++) {
                int idx = tid + 256 * i;
                int r = idx >> 3, c = (idx & 7) << 2;
                uint4 u = make_uint4(f2tf32(ra[i].x), f2tf32(ra[i].y), f2tf32(ra[i].z), f2tf32(ra[i].w));
                *(uint4*)&As[r][c] = u;
            }
#pragma unroll
            for (int i = 0; i < 4; i++) {
                int idx = tid + 256 * i;
                int kr = idx >> 5, c = (idx & 31) << 2;
                uint4 u = make_uint4(f2tf32(rb[i].x), f2tf32(rb[i].y), f2tf32(rb[i].z), f2tf32(rb[i].w));
                *(uint4*)&Bs[kr][c] = u;
            }
            __syncthreads();
        }
    }

    // epilogue
#pragma unroll
    for (int mt = 0; mt < 4; mt++) {
        int r0 = bm + wm * 64 + mt * 16 + g;
        int r1 = r0 + 8;
#pragma unroll
        for (int nt = 0; nt < 4; nt++) {
            int c = bn + wn * 32 + nt * 8 + t * 2;
            if (c < N) {
                if (OUT_HALF) {
                    __half* C = (__half*)Cv;
                    if (r0 < M)
                        *(__half2*)(C + (size_t)r0 * ldc + c) =
                            __float22half2_rn(make_float2(acc[mt][nt][0], acc[mt][nt][1]));
                    if (r1 < M)
                        *(__half2*)(C + (size_t)r1 * ldc + c) =
                            __float22half2_rn(make_float2(acc[mt][nt][2], acc[mt][nt][3]));
                } else {
                    float* C = (float*)Cv;
                    if (r0 < M)
                        *(float2*)(C + (size_t)r0 * ldc + c) =
                            make_float2(acc[mt][nt][0], acc[mt][nt][1]);
                    if (r1 < M)
                        *(float2*)(C + (size_t)r1 * ldc + c) =
                            make_float2(acc[mt][nt][2], acc[mt][nt][3]);
                }
            }
        }
    }
}

// ---------------- aggregation layer 1: fp16 gather, 32 lanes/node ----------------
__global__ void __launch_bounds__(256)
k_agg1() {
    int node = blockIdx.x * 8 + (threadIdx.x >> 5);
    int lane = threadIdx.x & 31;
    const __half* H = d_HAh;
    float di = d_dinv[node];
    float sw = di * di;

    const int coff = lane * 8;
    float acc[8];
    {
        uint4 u = *(const uint4*)(H + (size_t)node * HD1 + coff);
        const __half2* h2 = (const __half2*)&u;
#pragma unroll
        for (int j = 0; j < 4; j++) {
            float2 f = __half22float2(h2[j]);
            acc[2 * j] = f.x * sw;
            acc[2 * j + 1] = f.y * sw;
        }
    }

    int e = d_rp[node], e1 = d_rp[node + 1];
    for (; e + 1 < e1; e += 2) {
        int s0 = d_col[e];
        int s1 = d_col[e + 1];
        float w0 = di * d_dinv[s0];
        float w1 = di * d_dinv[s1];
        uint4 u0 = *(const uint4*)(H + (size_t)s0 * HD1 + coff);
        uint4 u1 = *(const uint4*)(H + (size_t)s1 * HD1 + coff);
        const __half2* a0 = (const __half2*)&u0;
        const __half2* a1 = (const __half2*)&u1;
#pragma unroll
        for (int j = 0; j < 4; j++) {
            float2 f0 = __half22float2(a0[j]);
            float2 f1 = __half22float2(a1[j]);
            acc[2 * j]     += f0.x * w0 + f1.x * w1;
            acc[2 * j + 1] += f0.y * w0 + f1.y * w1;
        }
    }
    if (e < e1) {
        int s0 = d_col[e];
        float w0 = di * d_dinv[s0];
        uint4 u0 = *(const uint4*)(H + (size_t)s0 * HD1 + coff);
        const __half2* a0 = (const __half2*)&u0;
#pragma unroll
        for (int j = 0; j < 4; j++) {
            float2 f0 = __half22float2(a0[j]);
            acc[2 * j]     += f0.x * w0;
            acc[2 * j + 1] += f0.y * w0;
        }
    }

    float* outp = d_HB + (size_t)node * HD1 + coff;
    float4 o0 = make_float4(softplusf(acc[0]), softplusf(acc[1]), softplusf(acc[2]), softplusf(acc[3]));
    float4 o1 = make_float4(softplusf(acc[4]), softplusf(acc[5]), softplusf(acc[6]), softplusf(acc[7]));
    *(float4*)outp = o0;
    *(float4*)(outp + 4) = o1;
}

// ---------------- aggregation layer 2 + epilogue: fp16 gather, 16 lanes/node ----------------
__global__ void __launch_bounds__(256)
k_agg2(float* __restrict__ out) {
    int node = blockIdx.x * 16 + (threadIdx.x >> 4);
    int lane = threadIdx.x & 15;
    const __half* H = d_HAh;   // reused, stride HD2P halves
    float di = d_dinv[node];
    float sw = di * di;

    const int coff = lane * 8;
    const __half* srow = H + (size_t)node * HD2P;
    float acc[8];
    {
        uint4 u = *(const uint4*)(srow + coff);
        const __half2* h2 = (const __half2*)&u;
#pragma unroll
        for (int j = 0; j < 4; j++) {
            float2 f = __half22float2(h2[j]);
            acc[2 * j] = f.x * sw;
            acc[2 * j + 1] = f.y * sw;
        }
    }
    float acck = (lane == 0) ? __half2float(srow[128]) * sw : 0.0f;

    int e = d_rp[node], e1 = d_rp[node + 1];
    for (; e + 1 < e1; e += 2) {
        int s0 = d_col[e];
        int s1 = d_col[e + 1];
        float w0 = di * d_dinv[s0];
        float w1 = di * d_dinv[s1];
        const __half* r0 = H + (size_t)s0 * HD2P;
        const __half* r1 = H + (size_t)s1 * HD2P;
        uint4 u0 = *(const uint4*)(r0 + coff);
        uint4 u1 = *(const uint4*)(r1 + coff);
        const __half2* a0 = (const __half2*)&u0;
        const __half2* a1 = (const __half2*)&u1;
#pragma unroll
        for (int j = 0; j < 4; j++) {
            float2 f0 = __half22float2(a0[j]);
            float2 f1 = __half22float2(a1[j]);
            acc[2 * j]     += f0.x * w0 + f1.x * w1;
            acc[2 * j + 1] += f0.y * w0 + f1.y * w1;
        }
        if (lane == 0) acck += __half2float(r0[128]) * w0 + __half2float(r1[128]) * w1;
    }
    if (e < e1) {
        int s0 = d_col[e];
        float w0 = di * d_dinv[s0];
        const __half* r0 = H + (size_t)s0 * HD2P;
        uint4 u0 = *(const uint4*)(r0 + coff);
        const __half2* a0 = (const __half2*)&u0;
#pragma unroll
        for (int j = 0; j < 4; j++) {
            float2 f0 = __half22float2(a0[j]);
            acc[2 * j]     += f0.x * w0;
            acc[2 * j + 1] += f0.y * w0;
        }
        if (lane == 0) acck += __half2float(r0[128]) * w0;
    }

    float lbd[8];
#pragma unroll
    for (int j = 0; j < 8; j++) lbd[j] = softplusf(acc[j]);

    float g = 0.0f, kap = 0.0f;
    if (lane == 0) {
        kap = softplusf(acck) + 0.1f;
        g = expf(lgammaf(1.0f + 1.0f / kap));
    }
    g = __shfl_sync(0xffffffffu, g, (threadIdx.x & 16), 32);

    const size_t ZOFF = 0;
    const size_t LOFF = (size_t)NN * 128;
    const size_t KOFF = (size_t)NN * 256;

    float* zp = out + ZOFF + (size_t)node * 128 + coff;
    float* lp = out + LOFF + (size_t)node * 128 + coff;
    *(float4*)zp       = make_float4(lbd[0] * g, lbd[1] * g, lbd[2] * g, lbd[3] * g);
    *(float4*)(zp + 4) = make_float4(lbd[4] * g, lbd[5] * g, lbd[6] * g, lbd[7] * g);
    *(float4*)lp       = make_float4(lbd[0], lbd[1], lbd[2], lbd[3]);
    *(float4*)(lp + 4) = make_float4(lbd[4], lbd[5], lbd[6], lbd[7]);
    if (lane == 0) out[KOFF + node] = kap;
}

// ---------------- launch ----------------
extern "C" void kernel_launch(void* const* d_in, const int* in_sizes, int n_in,
                              void* d_out, int out_size) {
    const float* x  = (const float*)d_in[0];
    const int* eidx = (const int*)d_in[1];
    const float* W0 = (const float*)d_in[2];
    const float* W1 = (const float*)d_in[3];
    float* out = (float*)d_out;

    const int* src = eidx;
    const int* dst = eidx + NE;

    __half* HAh; cudaGetSymbolAddress((void**)&HAh, d_HAh);
    float* HB;   cudaGetSymbolAddress((void**)&HB, d_HB);
    float* W1p;  cudaGetSymbolAddress((void**)&W1p, d_W1p);

    // CSR build — init MUST cover both d_cnt[NN] and d_W1p[HD1*HD2P]
    k_init<<<(INIT_N + 255) / 256, 256>>>(W1);
    k_hist<<<(NE + 255) / 256, 256>>>(dst);
    k_blocksum<<<NBLK, SCAN_B>>>();
    k_bscan<<<1, 128>>>();
    k_local<<<NBLK, SCAN_B>>>();
    k_fill<<<(NE + 255) / 256, 256>>>(src, dst);

    // GEMM1: HAh(fp16) = x @ W0  (50000x256, K=512)
    {
        dim3 grid((HD1 + 127) / 128, (NN + 127) / 128);
        k_gemm_tf32<true><<<grid, 256>>>(x, W0, HAh, NN, HD1, INDIM, INDIM, HD1, HD1);
    }
    // AGG1 + softplus -> HB (fp32)
    k_agg1<<<NN / 8, 256>>>();
    // GEMM2: HAh(fp16, stride 136) = HB @ W1p  (50000x136, K=256)
    {
        dim3 grid((HD2P + 127) / 128, (NN + 127) / 128);
        k_gemm_tf32<true><<<grid, 256>>>(HB, W1p, HAh, NN, HD2P, HD1, HD1, HD2P, HD2P);
    }
    // AGG2 + softplus + Weibull epilogue -> out
    k_agg2<<<NN / 16, 256>>>(out);
}

// round 7
// speedup vs baseline: 2.9190x; 1.2104x over previous
#include <cuda_runtime.h>
#include <cuda_fp16.h>
#include <math.h>
#include <stdint.h>

// Problem constants
#define NN    50000
#define NE    1600000
#define INDIM 512
#define HD1   256
#define HD2R  129     // real cols of layer 2
#define HD2P  136     // padded stride in halves (272B, 16B-aligned)

#define SCAN_B 512
#define NBLK   ((NN + SCAN_B - 1) / SCAN_B)   // 98

// init kernel must cover BOTH d_cnt[NN] and d_W1p[HD1*HD2P]
#define INIT_N ((NN) > (HD1 * HD2P) ? (NN) : (HD1 * HD2P))

// ---------------- static scratch (no allocations allowed) ----------------
__device__ __half d_HAh[(size_t)NN * HD1];  // fp16 XW0; reused as fp16 H1W1 (stride HD2P)
__device__ __half d_HB[(size_t)NN * HD1];   // fp16 softplus(agg1)
__device__ int    d_col[NE];
__device__ int    d_rp[NN + 1];
__device__ int    d_cur[NN];
__device__ int    d_cnt[NN];
__device__ float  d_dinv[NN];
__device__ float  d_W1p[HD1 * HD2P];
__device__ int    d_bsum[NBLK];
__device__ int    d_boff[NBLK];

// ---------------- helpers ----------------
__device__ __forceinline__ float softplusf(float x) {
    return fmaxf(x, 0.0f) + log1pf(expf(-fabsf(x)));
}

__device__ __forceinline__ void mma_f16(float c[4], const uint32_t a[4],
                                        uint32_t b0, uint32_t b1) {
    asm volatile(
        "mma.sync.aligned.m16n8k16.row.col.f32.f16.f16.f32 "
        "{%0,%1,%2,%3}, {%4,%5,%6,%7}, {%8,%9}, {%0,%1,%2,%3};\n"
        : "+f"(c[0]), "+f"(c[1]), "+f"(c[2]), "+f"(c[3])
        : "r"(a[0]), "r"(a[1]), "r"(a[2]), "r"(a[3]), "r"(b0), "r"(b1));
}

// ---------------- init: zero cnt + pad W1 (grid covers INIT_N) ----------------
__global__ void k_init(const float* __restrict__ W1) {
    int i = blockIdx.x * blockDim.x + threadIdx.x;
    if (i < NN) d_cnt[i] = 0;
    if (i < HD1 * HD2P) {
        int k = i / HD2P, n = i % HD2P;
        d_W1p[i] = (n < HD2R) ? W1[k * HD2R + n] : 0.0f;
    }
}

__global__ void k_hist(const int* __restrict__ dst) {
    int e = blockIdx.x * blockDim.x + threadIdx.x;
    if (e < NE) atomicAdd(&d_cnt[dst[e]], 1);
}

// ---------------- parallel scan: block sums -> 1-block scan -> local scan ----------------
__global__ void k_blocksum() {
    __shared__ int sh[SCAN_B];
    int t = threadIdx.x;
    int i = blockIdx.x * SCAN_B + t;
    sh[t] = (i < NN) ? d_cnt[i] : 0;
    __syncthreads();
    for (int off = SCAN_B / 2; off > 0; off >>= 1) {
        if (t < off) sh[t] += sh[t + off];
        __syncthreads();
    }
    if (t == 0) d_bsum[blockIdx.x] = sh[0];
}

__global__ void k_bscan() {
    __shared__ int sh[128];
    int t = threadIdx.x;
    int v = (t < NBLK) ? d_bsum[t] : 0;
    sh[t] = v;
    __syncthreads();
    for (int off = 1; off < 128; off <<= 1) {
        int add = (t >= off) ? sh[t - off] : 0;
        __syncthreads();
        sh[t] += add;
        __syncthreads();
    }
    if (t < NBLK) d_boff[t] = sh[t] - v;   // exclusive
}

__global__ void k_local() {
    __shared__ int sh[SCAN_B];
    int t = threadIdx.x;
    int i = blockIdx.x * SCAN_B + t;
    int v = (i < NN) ? d_cnt[i] : 0;
    sh[t] = v;
    __syncthreads();
    for (int off = 1; off < SCAN_B; off <<= 1) {
        int add = (t >= off) ? sh[t - off] : 0;
        __syncthreads();
        sh[t] += add;
        __syncthreads();
    }
    if (i < NN) {
        int incl = sh[t];
        int base = d_boff[blockIdx.x] + incl - v;
        d_rp[i] = base;
        d_cur[i] = base;
        d_dinv[i] = rsqrtf((float)v + 1.0f);
        if (i == NN - 1) d_rp[NN] = d_boff[blockIdx.x] + incl;
    }
}

__global__ void k_fill(const int* __restrict__ src, const int* __restrict__ dst) {
    int e = blockIdx.x * blockDim.x + threadIdx.x;
    if (e >= NE) return;
    int s = src[e], d = dst[e];
    int p = atomicAdd(&d_cur[d], 1);
    d_col[p] = s;
}

// ---------------- fp16 tensor-core GEMM: 128x128 tile, BK=32, 256 threads ----------------
// A: fp32 (A_HALF=false) or fp16 (A_HALF=true) row-major MxK
// B: fp32 row-major KxN (converted to fp16 in smem)
// C: fp16 (OUT_HALF) or fp32
template <bool A_HALF, bool OUT_HALF>
__global__ void __launch_bounds__(256, 1)
k_gemm_f16(const void* __restrict__ Av, const float* __restrict__ Bg,
           void* __restrict__ Cv, int M, int N, int K,
           int lda, int ldb, int ldc) {
    constexpr int SA = 40;    // A smem stride in halves (80B -> conflict-free LDSM)
    constexpr int SB = 136;   // B smem stride in halves (272B -> conflict-free LDSM)
    __shared__ __half As[128 * SA];
    __shared__ __half Bs[32 * SB];

    const int tid = threadIdx.x;
    const int warp = tid >> 5, lane = tid & 31;
    const int wm = warp >> 2, wn = warp & 3;
    const int g = lane >> 2, t = lane & 3;
    const int bm = blockIdx.y * 128, bn = blockIdx.x * 128;

    const int l8 = lane & 7;
    const int lm8 = (lane >> 3) & 1;
    const int lk8 = lane >> 4;
    const int arow_off = l8 + (lm8 << 3);

    const uint32_t as_base = (uint32_t)__cvta_generic_to_shared(As);
    const uint32_t bs_base = (uint32_t)__cvta_generic_to_shared(Bs);

    float acc[4][4][4];
#pragma unroll
    for (int mt = 0; mt < 4; mt++)
#pragma unroll
        for (int nt = 0; nt < 4; nt++)
#pragma unroll
            for (int j = 0; j < 4; j++) acc[mt][nt][j] = 0.0f;

    uint4  raH[2];            // fp16 A: 2 x (8 halves) per thread per tile
    float4 raF[4];
    float4 rbF[4];

    auto loadA = [&](int k0) {
        if (A_HALF) {
            const __half* A = (const __half*)Av;
#pragma unroll
            for (int i = 0; i < 2; i++) {
                int idx = tid + 256 * i;
                int r = idx >> 2, c = (idx & 3) << 3;   // 8-half steps
                int gr = bm + r;
                uint4 v = make_uint4(0u, 0u, 0u, 0u);
                if (gr < M) v = *(const uint4*)(A + (size_t)gr * lda + k0 + c);  // 16B = 8 halves
                raH[i] = v;
            }
        } else {
            const float* A = (const float*)Av;
#pragma unroll
            for (int i = 0; i < 4; i++) {
                int idx = tid + 256 * i;
                int r = idx >> 3, c = (idx & 7) << 2;
                int gr = bm + r;
                float4 v = make_float4(0.f, 0.f, 0.f, 0.f);
                if (gr < M) v = *(const float4*)(A + (size_t)gr * lda + k0 + c);
                raF[i] = v;
            }
        }
    };
    auto loadB = [&](int k0) {
#pragma unroll
        for (int i = 0; i < 4; i++) {
            int idx = tid + 256 * i;
            int kr = idx >> 5, c = (idx & 31) << 2;
            int gc = bn + c;
            float4 v = make_float4(0.f, 0.f, 0.f, 0.f);
            if (gc < N) v = *(const float4*)(Bg + (size_t)(k0 + kr) * ldb + gc);
            rbF[i] = v;
        }
    };
    auto storeA = [&]() {
        if (A_HALF) {
#pragma unroll
            for (int i = 0; i < 2; i++) {
                int idx = tid + 256 * i;
                int r = idx >> 2, c = (idx & 3) << 3;
                *(uint4*)&As[r * SA + c] = raH[i];     // 8 halves
            }
        } else {
#pragma unroll
            for (int i = 0; i < 4; i++) {
                int idx = tid + 256 * i;
                int r = idx >> 3, c = (idx & 7) << 2;
                __half2 h0 = __float22half2_rn(make_float2(raF[i].x, raF[i].y));
                __half2 h1 = __float22half2_rn(make_float2(raF[i].z, raF[i].w));
                uint2 u;
                u.x = *(uint32_t*)&h0;
                u.y = *(uint32_t*)&h1;
                *(uint2*)&As[r * SA + c] = u;
            }
        }
    };
    auto storeB = [&]() {
#pragma unroll
        for (int i = 0; i < 4; i++) {
            int idx = tid + 256 * i;
            int kr = idx >> 5, c = (idx & 31) << 2;
            __half2 h0 = __float22half2_rn(make_float2(rbF[i].x, rbF[i].y));
            __half2 h1 = __float22half2_rn(make_float2(rbF[i].z, rbF[i].w));
            uint2 u;
            u.x = *(uint32_t*)&h0;
            u.y = *(uint32_t*)&h1;
            *(uint2*)&Bs[kr * SB + c] = u;
        }
    };

    loadA(0); loadB(0); storeA(); storeB();
    __syncthreads();

    const int nIter = K >> 5;
    for (int it = 0; it < nIter; it++) {
        if (it + 1 < nIter) { loadA((it + 1) << 5); loadB((it + 1) << 5); }
#pragma unroll
        for (int kk = 0; kk < 2; kk++) {
            uint32_t a[4][4], b[2][4];
            const int acol = (kk << 4) + (lk8 << 3);
#pragma unroll
            for (int mt = 0; mt < 4; mt++) {
                int row = wm * 64 + mt * 16 + arow_off;
                uint32_t addr = as_base + (uint32_t)(row * SA + acol) * 2u;
                asm volatile(
                    "ldmatrix.sync.aligned.m8n8.x4.shared.b16 {%0,%1,%2,%3}, [%4];"
                    : "=r"(a[mt][0]), "=r"(a[mt][1]), "=r"(a[mt][2]), "=r"(a[mt][3])
                    : "r"(addr));
            }
            const int brow = (kk << 4) + arow_off;
#pragma unroll
            for (int h = 0; h < 2; h++) {
                int ncol = wn * 32 + (h << 4) + (lk8 << 3);
                uint32_t addr = bs_base + (uint32_t)(brow * SB + ncol) * 2u;
                asm volatile(
                    "ldmatrix.sync.aligned.m8n8.x4.trans.shared.b16 {%0,%1,%2,%3}, [%4];"
                    : "=r"(b[h][0]), "=r"(b[h][1]), "=r"(b[h][2]), "=r"(b[h][3])
                    : "r"(addr));
            }
#pragma unroll
            for (int mt = 0; mt < 4; mt++)
#pragma unroll
                for (int nt = 0; nt < 4; nt++)
                    mma_f16(acc[mt][nt], a[mt],
                            b[nt >> 1][(nt & 1) * 2], b[nt >> 1][(nt & 1) * 2 + 1]);
        }
        __syncthreads();
        if (it + 1 < nIter) {
            storeA(); storeB();
            __syncthreads();
        }
    }

    // epilogue: thread(g,t) holds C[r][2t],C[r][2t+1] (c0,c1) and C[r+8][...] (c2,c3)
#pragma unroll
    for (int mt = 0; mt < 4; mt++) {
        int r0 = bm + wm * 64 + mt * 16 + g;
        int r1 = r0 + 8;
#pragma unroll
        for (int nt = 0; nt < 4; nt++) {
            int c = bn + wn * 32 + nt * 8 + t * 2;
            if (c < N) {
                if (OUT_HALF) {
                    __half* C = (__half*)Cv;
                    if (r0 < M)
                        *(__half2*)(C + (size_t)r0 * ldc + c) =
                            __float22half2_rn(make_float2(acc[mt][nt][0], acc[mt][nt][1]));
                    if (r1 < M)
                        *(__half2*)(C + (size_t)r1 * ldc + c) =
                            __float22half2_rn(make_float2(acc[mt][nt][2], acc[mt][nt][3]));
                } else {
                    float* C = (float*)Cv;
                    if (r0 < M)
                        *(float2*)(C + (size_t)r0 * ldc + c) =
                            make_float2(acc[mt][nt][0], acc[mt][nt][1]);
                    if (r1 < M)
                        *(float2*)(C + (size_t)r1 * ldc + c) =
                            make_float2(acc[mt][nt][2], acc[mt][nt][3]);
                }
            }
        }
    }
}

// ---------------- aggregation layer 1: fp16 gather, 32 lanes/node -> fp16 out ----------------
__global__ void __launch_bounds__(256)
k_agg1() {
    int node = blockIdx.x * 8 + (threadIdx.x >> 5);
    int lane = threadIdx.x & 31;
    const __half* H = d_HAh;
    float di = d_dinv[node];
    float sw = di * di;

    const int coff = lane * 8;
    float acc[8];
    {
        uint4 u = *(const uint4*)(H + (size_t)node * HD1 + coff);
        const __half2* h2 = (const __half2*)&u;
#pragma unroll
        for (int j = 0; j < 4; j++) {
            float2 f = __half22float2(h2[j]);
            acc[2 * j] = f.x * sw;
            acc[2 * j + 1] = f.y * sw;
        }
    }

    int e = d_rp[node], e1 = d_rp[node + 1];
    for (; e + 1 < e1; e += 2) {
        int s0 = d_col[e];
        int s1 = d_col[e + 1];
        float w0 = di * d_dinv[s0];
        float w1 = di * d_dinv[s1];
        uint4 u0 = *(const uint4*)(H + (size_t)s0 * HD1 + coff);
        uint4 u1 = *(const uint4*)(H + (size_t)s1 * HD1 + coff);
        const __half2* a0 = (const __half2*)&u0;
        const __half2* a1 = (const __half2*)&u1;
#pragma unroll
        for (int j = 0; j < 4; j++) {
            float2 f0 = __half22float2(a0[j]);
            float2 f1 = __half22float2(a1[j]);
            acc[2 * j]     += f0.x * w0 + f1.x * w1;
            acc[2 * j + 1] += f0.y * w0 + f1.y * w1;
        }
    }
    if (e < e1) {
        int s0 = d_col[e];
        float w0 = di * d_dinv[s0];
        uint4 u0 = *(const uint4*)(H + (size_t)s0 * HD1 + coff);
        const __half2* a0 = (const __half2*)&u0;
#pragma unroll
        for (int j = 0; j < 4; j++) {
            float2 f0 = __half22float2(a0[j]);
            acc[2 * j]     += f0.x * w0;
            acc[2 * j + 1] += f0.y * w0;
        }
    }

    __half* outp = d_HB + (size_t)node * HD1 + coff;
    __half2 p0 = __float22half2_rn(make_float2(softplusf(acc[0]), softplusf(acc[1])));
    __half2 p1 = __float22half2_rn(make_float2(softplusf(acc[2]), softplusf(acc[3])));
    __half2 p2 = __float22half2_rn(make_float2(softplusf(acc[4]), softplusf(acc[5])));
    __half2 p3 = __float22half2_rn(make_float2(softplusf(acc[6]), softplusf(acc[7])));
    uint4 st;
    st.x = *(uint32_t*)&p0;
    st.y = *(uint32_t*)&p1;
    st.z = *(uint32_t*)&p2;
    st.w = *(uint32_t*)&p3;
    *(uint4*)outp = st;
}

// ---------------- aggregation layer 2 + epilogue: fp16 gather, 16 lanes/node ----------------
__global__ void __launch_bounds__(256)
k_agg2(float* __restrict__ out) {
    int node = blockIdx.x * 16 + (threadIdx.x >> 4);
    int lane = threadIdx.x & 15;
    const __half* H = d_HAh;   // reused, stride HD2P halves
    float di = d_dinv[node];
    float sw = di * di;

    const int coff = lane * 8;
    const __half* srow = H + (size_t)node * HD2P;
    float acc[8];
    {
        uint4 u = *(const uint4*)(srow + coff);
        const __half2* h2 = (const __half2*)&u;
#pragma unroll
        for (int j = 0; j < 4; j++) {
            float2 f = __half22float2(h2[j]);
            acc[2 * j] = f.x * sw;
            acc[2 * j + 1] = f.y * sw;
        }
    }
    float acck = (lane == 0) ? __half2float(srow[128]) * sw : 0.0f;

    int e = d_rp[node], e1 = d_rp[node + 1];
    for (; e + 1 < e1; e += 2) {
        int s0 = d_col[e];
        int s1 = d_col[e + 1];
        float w0 = di * d_dinv[s0];
        float w1 = di * d_dinv[s1];
        const __half* r0 = H + (size_t)s0 * HD2P;
        const __half* r1 = H + (size_t)s1 * HD2P;
        uint4 u0 = *(const uint4*)(r0 + coff);
        uint4 u1 = *(const uint4*)(r1 + coff);
        const __half2* a0 = (const __half2*)&u0;
        const __half2* a1 = (const __half2*)&u1;
#pragma unroll
        for (int j = 0; j < 4; j++) {
            float2 f0 = __half22float2(a0[j]);
            float2 f1 = __half22float2(a1[j]);
            acc[2 * j]     += f0.x * w0 + f1.x * w1;
            acc[2 * j + 1] += f0.y * w0 + f1.y * w1;
        }
        if (lane == 0) acck += __half2float(r0[128]) * w0 + __half2float(r1[128]) * w1;
    }
    if (e < e1) {
        int s0 = d_col[e];
        float w0 = di * d_dinv[s0];
        const __half* r0 = H + (size_t)s0 * HD2P;
        uint4 u0 = *(const uint4*)(r0 + coff);
        const __half2* a0 = (const __half2*)&u0;
#pragma unroll
        for (int j = 0; j < 4; j++) {
            float2 f0 = __half22float2(a0[j]);
            acc[2 * j]     += f0.x * w0;
            acc[2 * j + 1] += f0.y * w0;
        }
        if (lane == 0) acck += __half2float(r0[128]) * w0;
    }

    float lbd[8];
#pragma unroll
    for (int j = 0; j < 8; j++) lbd[j] = softplusf(acc[j]);

    float g = 0.0f, kap = 0.0f;
    if (lane == 0) {
        kap = softplusf(acck) + 0.1f;
        g = expf(lgammaf(1.0f + 1.0f / kap));
    }
    g = __shfl_sync(0xffffffffu, g, (threadIdx.x & 16), 32);

    const size_t ZOFF = 0;
    const size_t LOFF = (size_t)NN * 128;
    const size_t KOFF = (size_t)NN * 256;

    float* zp = out + ZOFF + (size_t)node * 128 + coff;
    float* lp = out + LOFF + (size_t)node * 128 + coff;
    *(float4*)zp       = make_float4(lbd[0] * g, lbd[1] * g, lbd[2] * g, lbd[3] * g);
    *(float4*)(zp + 4) = make_float4(lbd[4] * g, lbd[5] * g, lbd[6] * g, lbd[7] * g);
    *(float4*)lp       = make_float4(lbd[0], lbd[1], lbd[2], lbd[3]);
    *(float4*)(lp + 4) = make_float4(lbd[4], lbd[5], lbd[6], lbd[7]);
    if (lane == 0) out[KOFF + node] = kap;
}

// ---------------- launch ----------------
extern "C" void kernel_launch(void* const* d_in, const int* in_sizes, int n_in,
                              void* d_out, int out_size) {
    const float* x  = (const float*)d_in[0];
    const int* eidx = (const int*)d_in[1];
    const float* W0 = (const float*)d_in[2];
    const float* W1 = (const float*)d_in[3];
    float* out = (float*)d_out;

    const int* src = eidx;
    const int* dst = eidx + NE;

    __half* HAh; cudaGetSymbolAddress((void**)&HAh, d_HAh);
    __half* HB;  cudaGetSymbolAddress((void**)&HB, d_HB);
    float* W1p;  cudaGetSymbolAddress((void**)&W1p, d_W1p);

    // Fork a side stream for the CSR build so it overlaps GEMM1 (proven capture-legal in R6).
    cudaStream_t s1;
    cudaStreamCreateWithFlags(&s1, cudaStreamNonBlocking);
    cudaEvent_t ef, ej;
    cudaEventCreateWithFlags(&ef, cudaEventDisableTiming);
    cudaEventCreateWithFlags(&ej, cudaEventDisableTiming);

    cudaEventRecord(ef, 0);
    cudaStreamWaitEvent(s1, ef, 0);

    // CSR build on side stream
    k_init<<<(INIT_N + 255) / 256, 256, 0, s1>>>(W1);
    k_hist<<<(NE + 255) / 256, 256, 0, s1>>>(dst);
    k_blocksum<<<NBLK, SCAN_B, 0, s1>>>();
    k_bscan<<<1, 128, 0, s1>>>();
    k_local<<<NBLK, SCAN_B, 0, s1>>>();
    k_fill<<<(NE + 255) / 256, 256, 0, s1>>>(src, dst);
    cudaEventRecord(ej, s1);

    // GEMM1 on main stream, concurrent with CSR build:
    // HAh(fp16) = x @ W0  (50000x256, K=512)
    {
        dim3 grid((HD1 + 127) / 128, (NN + 127) / 128);
        k_gemm_f16<false, true><<<grid, 256>>>(x, W0, HAh, NN, HD1, INDIM, INDIM, HD1, HD1);
    }

    // join: agg1 needs both GEMM1 and CSR
    cudaStreamWaitEvent(0, ej, 0);

    // AGG1 + softplus -> HB (fp16)
    k_agg1<<<NN / 8, 256>>>();
    // GEMM2: HAh(fp16, stride 136) = HB(fp16) @ W1p  (50000x136, K=256)
    {
        dim3 grid((HD2P + 127) / 128, (NN + 127) / 128);
        k_gemm_f16<true, true><<<grid, 256>>>(HB, W1p, HAh, NN, HD2P, HD1, HD1, HD2P, HD2P);
    }
    // AGG2 + softplus + Weibull epilogue -> out
    k_agg2<<<NN / 16, 256>>>(out);
}

// round 8
// speedup vs baseline: 2.9341x; 1.0052x over previous
#include <cuda_runtime.h>
#include <cuda_fp16.h>
#include <math.h>
#include <stdint.h>

// Problem constants
#define NN    50000
#define NE    1600000
#define INDIM 512
#define HD1   256
#define HD2R  129     // real cols of layer 2
#define HD2P  136     // padded stride in halves (272B, 16B-aligned)
#define NHALF 25000   // node split for agg1/GEMM2 pipeline

#define SCAN_B 512
#define NBLK   ((NN + SCAN_B - 1) / SCAN_B)   // 98

// init kernel must cover BOTH d_cnt[NN] and d_W1p[HD1*HD2P]
#define INIT_N ((NN) > (HD1 * HD2P) ? (NN) : (HD1 * HD2P))

// ---------------- static scratch (no allocations allowed) ----------------
__device__ __half d_HAh[(size_t)NN * HD1];  // fp16 XW0; reused as fp16 H1W1 (stride HD2P)
__device__ __half d_HB[(size_t)NN * HD1];   // fp16 softplus(agg1)
__device__ int    d_col[NE];
__device__ int    d_rp[NN + 1];
__device__ int    d_cur[NN];
__device__ int    d_cnt[NN];
__device__ float  d_dinv[NN];
__device__ float  d_W1p[HD1 * HD2P];
__device__ int    d_bsum[NBLK];
__device__ int    d_boff[NBLK];

// ---------------- helpers ----------------
__device__ __forceinline__ float softplusf(float x) {
    return fmaxf(x, 0.0f) + log1pf(expf(-fabsf(x)));
}

__device__ __forceinline__ void mma_f16(float c[4], const uint32_t a[4],
                                        uint32_t b0, uint32_t b1) {
    asm volatile(
        "mma.sync.aligned.m16n8k16.row.col.f32.f16.f16.f32 "
        "{%0,%1,%2,%3}, {%4,%5,%6,%7}, {%8,%9}, {%0,%1,%2,%3};\n"
        : "+f"(c[0]), "+f"(c[1]), "+f"(c[2]), "+f"(c[3])
        : "r"(a[0]), "r"(a[1]), "r"(a[2]), "r"(a[3]), "r"(b0), "r"(b1));
}

// ---------------- init: zero cnt + pad W1 (grid covers INIT_N) ----------------
__global__ void k_init(const float* __restrict__ W1) {
    int i = blockIdx.x * blockDim.x + threadIdx.x;
    if (i < NN) d_cnt[i] = 0;
    if (i < HD1 * HD2P) {
        int k = i / HD2P, n = i % HD2P;
        d_W1p[i] = (n < HD2R) ? W1[k * HD2R + n] : 0.0f;
    }
}

// 4 edges per thread, vectorized index load
__global__ void k_hist(const int4* __restrict__ dst4) {
    int e = blockIdx.x * blockDim.x + threadIdx.x;
    if (e < NE / 4) {
        int4 d = dst4[e];
        atomicAdd(&d_cnt[d.x], 1);
        atomicAdd(&d_cnt[d.y], 1);
        atomicAdd(&d_cnt[d.z], 1);
        atomicAdd(&d_cnt[d.w], 1);
    }
}

// ---------------- parallel scan: block sums -> 1-block scan -> local scan ----------------
__global__ void k_blocksum() {
    __shared__ int sh[SCAN_B];
    int t = threadIdx.x;
    int i = blockIdx.x * SCAN_B + t;
    sh[t] = (i < NN) ? d_cnt[i] : 0;
    __syncthreads();
    for (int off = SCAN_B / 2; off > 0; off >>= 1) {
        if (t < off) sh[t] += sh[t + off];
        __syncthreads();
    }
    if (t == 0) d_bsum[blockIdx.x] = sh[0];
}

__global__ void k_bscan() {
    __shared__ int sh[128];
    int t = threadIdx.x;
    int v = (t < NBLK) ? d_bsum[t] : 0;
    sh[t] = v;
    __syncthreads();
    for (int off = 1; off < 128; off <<= 1) {
        int add = (t >= off) ? sh[t - off] : 0;
        __syncthreads();
        sh[t] += add;
        __syncthreads();
    }
    if (t < NBLK) d_boff[t] = sh[t] - v;   // exclusive
}

__global__ void k_local() {
    __shared__ int sh[SCAN_B];
    int t = threadIdx.x;
    int i = blockIdx.x * SCAN_B + t;
    int v = (i < NN) ? d_cnt[i] : 0;
    sh[t] = v;
    __syncthreads();
    for (int off = 1; off < SCAN_B; off <<= 1) {
        int add = (t >= off) ? sh[t - off] : 0;
        __syncthreads();
        sh[t] += add;
        __syncthreads();
    }
    if (i < NN) {
        int incl = sh[t];
        int base = d_boff[blockIdx.x] + incl - v;
        d_rp[i] = base;
        d_cur[i] = base;
        d_dinv[i] = rsqrtf((float)v + 1.0f);
        if (i == NN - 1) d_rp[NN] = d_boff[blockIdx.x] + incl;
    }
}

__global__ void k_fill(const int4* __restrict__ src4, const int4* __restrict__ dst4) {
    int e = blockIdx.x * blockDim.x + threadIdx.x;
    if (e >= NE / 4) return;
    int4 s = src4[e];
    int4 d = dst4[e];
    d_col[atomicAdd(&d_cur[d.x], 1)] = s.x;
    d_col[atomicAdd(&d_cur[d.y], 1)] = s.y;
    d_col[atomicAdd(&d_cur[d.z], 1)] = s.z;
    d_col[atomicAdd(&d_cur[d.w], 1)] = s.w;
}

// ---------------- fp16 tensor-core GEMM: 128xBN tile, BK=32, 256 threads ----------------
// A: fp32 (A_HALF=false) or fp16 (A_HALF=true) row-major MxK
// B: fp32 row-major KxN (converted to fp16 in smem)
// C: fp16 (OUT_HALF) or fp32.  BN in {64, 128}.
template <bool A_HALF, bool OUT_HALF, int BN>
__global__ void __launch_bounds__(256, 1)
k_gemm_f16(const void* __restrict__ Av, const float* __restrict__ Bg,
           void* __restrict__ Cv, int M, int N, int K,
           int lda, int ldb, int ldc) {
    constexpr int NT = BN / 32;      // n-tiles (8 cols) per warp
    constexpr int SA = 40;           // A smem stride (halves) -> conflict-free LDSM
    constexpr int SB = BN + 8;       // B smem stride (halves) -> conflict-free LDSM
    constexpr int LB = BN / 32;      // B float4 loads per thread per tile
    constexpr int BNQ = BN / 4;      // B float4s per k-row
    __shared__ __half As[128 * SA];
    __shared__ __half Bs[32 * SB];

    const int tid = threadIdx.x;
    const int warp = tid >> 5, lane = tid & 31;
    const int wm = warp >> 2, wn = warp & 3;
    const int g = lane >> 2, t = lane & 3;
    const int bm = blockIdx.y * 128, bn = blockIdx.x * BN;

    const int l8 = lane & 7;
    const int lm8 = (lane >> 3) & 1;
    const int lk8 = lane >> 4;
    const int arow_off = l8 + (lm8 << 3);

    const uint32_t as_base = (uint32_t)__cvta_generic_to_shared(As);
    const uint32_t bs_base = (uint32_t)__cvta_generic_to_shared(Bs);

    float acc[4][NT][4];
#pragma unroll
    for (int mt = 0; mt < 4; mt++)
#pragma unroll
        for (int nt = 0; nt < NT; nt++)
#pragma unroll
            for (int j = 0; j < 4; j++) acc[mt][nt][j] = 0.0f;

    uint4  raH[2];            // fp16 A: 2 x (8 halves) per thread per tile
    float4 raF[4];
    float4 rbF[LB];

    auto loadA = [&](int k0) {
        if (A_HALF) {
            const __half* A = (const __half*)Av;
#pragma unroll
            for (int i = 0; i < 2; i++) {
                int idx = tid + 256 * i;
                int r = idx >> 2, c = (idx & 3) << 3;   // 8-half steps
                int gr = bm + r;
                uint4 v = make_uint4(0u, 0u, 0u, 0u);
                if (gr < M) v = *(const uint4*)(A + (size_t)gr * lda + k0 + c);
                raH[i] = v;
            }
        } else {
            const float* A = (const float*)Av;
#pragma unroll
            for (int i = 0; i < 4; i++) {
                int idx = tid + 256 * i;
                int r = idx >> 3, c = (idx & 7) << 2;
                int gr = bm + r;
                float4 v = make_float4(0.f, 0.f, 0.f, 0.f);
                if (gr < M) v = *(const float4*)(A + (size_t)gr * lda + k0 + c);
                raF[i] = v;
            }
        }
    };
    auto loadB = [&](int k0) {
#pragma unroll
        for (int i = 0; i < LB; i++) {
            int idx = tid + 256 * i;
            int kr = idx / BNQ, c = (idx % BNQ) << 2;
            int gc = bn + c;
            float4 v = make_float4(0.f, 0.f, 0.f, 0.f);
            if (gc < N) v = *(const float4*)(Bg + (size_t)(k0 + kr) * ldb + gc);
            rbF[i] = v;
        }
    };
    auto storeA = [&]() {
        if (A_HALF) {
#pragma unroll
            for (int i = 0; i < 2; i++) {
                int idx = tid + 256 * i;
                int r = idx >> 2, c = (idx & 3) << 3;
                *(uint4*)&As[r * SA + c] = raH[i];
            }
        } else {
#pragma unroll
            for (int i = 0; i < 4; i++) {
                int idx = tid + 256 * i;
                int r = idx >> 3, c = (idx & 7) << 2;
                __half2 h0 = __float22half2_rn(make_float2(raF[i].x, raF[i].y));
                __half2 h1 = __float22half2_rn(make_float2(raF[i].z, raF[i].w));
                uint2 u;
                u.x = *(uint32_t*)&h0;
                u.y = *(uint32_t*)&h1;
                *(uint2*)&As[r * SA + c] = u;
            }
        }
    };
    auto storeB = [&]() {
#pragma unroll
        for (int i = 0; i < LB; i++) {
            int idx = tid + 256 * i;
            int kr = idx / BNQ, c = (idx % BNQ) << 2;
            __half2 h0 = __float22half2_rn(make_float2(rbF[i].x, rbF[i].y));
            __half2 h1 = __float22half2_rn(make_float2(rbF[i].z, rbF[i].w));
            uint2 u;
            u.x = *(uint32_t*)&h0;
            u.y = *(uint32_t*)&h1;
            *(uint2*)&Bs[kr * SB + c] = u;
        }
    };

    loadA(0); loadB(0); storeA(); storeB();
    __syncthreads();

    const int nIter = K >> 5;
    for (int it = 0; it < nIter; it++) {
        if (it + 1 < nIter) { loadA((it + 1) << 5); loadB((it + 1) << 5); }
#pragma unroll
        for (int kk = 0; kk < 2; kk++) {
            uint32_t a[4][4], b[NT / 2][4];
            const int acol = (kk << 4) + (lk8 << 3);
#pragma unroll
            for (int mt = 0; mt < 4; mt++) {
                int row = wm * 64 + mt * 16 + arow_off;
                uint32_t addr = as_base + (uint32_t)(row * SA + acol) * 2u;
                asm volatile(
                    "ldmatrix.sync.aligned.m8n8.x4.shared.b16 {%0,%1,%2,%3}, [%4];"
                    : "=r"(a[mt][0]), "=r"(a[mt][1]), "=r"(a[mt][2]), "=r"(a[mt][3])
                    : "r"(addr));
            }
            const int brow = (kk << 4) + arow_off;
#pragma unroll
            for (int h = 0; h < NT / 2; h++) {
                int ncol = wn * (NT * 8) + (h << 4) + (lk8 << 3);
                uint32_t addr = bs_base + (uint32_t)(brow * SB + ncol) * 2u;
                asm volatile(
                    "ldmatrix.sync.aligned.m8n8.x4.trans.shared.b16 {%0,%1,%2,%3}, [%4];"
                    : "=r"(b[h][0]), "=r"(b[h][1]), "=r"(b[h][2]), "=r"(b[h][3])
                    : "r"(addr));
            }
#pragma unroll
            for (int mt = 0; mt < 4; mt++)
#pragma unroll
                for (int nt = 0; nt < NT; nt++)
                    mma_f16(acc[mt][nt], a[mt],
                            b[nt >> 1][(nt & 1) * 2], b[nt >> 1][(nt & 1) * 2 + 1]);
        }
        __syncthreads();
        if (it + 1 < nIter) {
            storeA(); storeB();
            __syncthreads();
        }
    }

    // epilogue
#pragma unroll
    for (int mt = 0; mt < 4; mt++) {
        int r0 = bm + wm * 64 + mt * 16 + g;
        int r1 = r0 + 8;
#pragma unroll
        for (int nt = 0; nt < NT; nt++) {
            int c = bn + wn * (NT * 8) + nt * 8 + t * 2;
            if (c < N) {
                if (OUT_HALF) {
                    __half* C = (__half*)Cv;
                    if (r0 < M)
                        *(__half2*)(C + (size_t)r0 * ldc + c) =
                            __float22half2_rn(make_float2(acc[mt][nt][0], acc[mt][nt][1]));
                    if (r1 < M)
                        *(__half2*)(C + (size_t)r1 * ldc + c) =
                            __float22half2_rn(make_float2(acc[mt][nt][2], acc[mt][nt][3]));
                } else {
                    float* C = (float*)Cv;
                    if (r0 < M)
                        *(float2*)(C + (size_t)r0 * ldc + c) =
                            make_float2(acc[mt][nt][0], acc[mt][nt][1]);
                    if (r1 < M)
                        *(float2*)(C + (size_t)r1 * ldc + c) =
                            make_float2(acc[mt][nt][2], acc[mt][nt][3]);
                }
            }
        }
    }
}

// ---------------- aggregation layer 1: fp16 gather, 32 lanes/node -> fp16 out ----------------
// processes nodes [base, base + 8*gridDim.x)
__global__ void __launch_bounds__(256)
k_agg1(int base) {
    int node = base + blockIdx.x * 8 + (threadIdx.x >> 5);
    int lane = threadIdx.x & 31;
    const __half* H = d_HAh;
    float di = d_dinv[node];
    float sw = di * di;

    const int coff = lane * 8;
    float acc[8];
    {
        uint4 u = *(const uint4*)(H + (size_t)node * HD1 + coff);
        const __half2* h2 = (const __half2*)&u;
#pragma unroll
        for (int j = 0; j < 4; j++) {
            float2 f = __half22float2(h2[j]);
            acc[2 * j] = f.x * sw;
            acc[2 * j + 1] = f.y * sw;
        }
    }

    int e = d_rp[node], e1 = d_rp[node + 1];
    for (; e + 3 < e1; e += 4) {
        int s0 = d_col[e], s1 = d_col[e + 1], s2 = d_col[e + 2], s3 = d_col[e + 3];
        float w0 = di * d_dinv[s0];
        float w1 = di * d_dinv[s1];
        float w2 = di * d_dinv[s2];
        float w3 = di * d_dinv[s3];
        uint4 u0 = *(const uint4*)(H + (size_t)s0 * HD1 + coff);
        uint4 u1 = *(const uint4*)(H + (size_t)s1 * HD1 + coff);
        uint4 u2 = *(const uint4*)(H + (size_t)s2 * HD1 + coff);
        uint4 u3 = *(const uint4*)(H + (size_t)s3 * HD1 + coff);
        const __half2* a0 = (const __half2*)&u0;
        const __half2* a1 = (const __half2*)&u1;
        const __half2* a2 = (const __half2*)&u2;
        const __half2* a3 = (const __half2*)&u3;
#pragma unroll
        for (int j = 0; j < 4; j++) {
            float2 f0 = __half22float2(a0[j]);
            float2 f1 = __half22float2(a1[j]);
            float2 f2 = __half22float2(a2[j]);
            float2 f3 = __half22float2(a3[j]);
            acc[2 * j]     += f0.x * w0 + f1.x * w1 + f2.x * w2 + f3.x * w3;
            acc[2 * j + 1] += f0.y * w0 + f1.y * w1 + f2.y * w2 + f3.y * w3;
        }
    }
    for (; e < e1; e++) {
        int s0 = d_col[e];
        float w0 = di * d_dinv[s0];
        uint4 u0 = *(const uint4*)(H + (size_t)s0 * HD1 + coff);
        const __half2* a0 = (const __half2*)&u0;
#pragma unroll
        for (int j = 0; j < 4; j++) {
            float2 f0 = __half22float2(a0[j]);
            acc[2 * j]     += f0.x * w0;
            acc[2 * j + 1] += f0.y * w0;
        }
    }

    __half* outp = d_HB + (size_t)node * HD1 + coff;
    __half2 p0 = __float22half2_rn(make_float2(softplusf(acc[0]), softplusf(acc[1])));
    __half2 p1 = __float22half2_rn(make_float2(softplusf(acc[2]), softplusf(acc[3])));
    __half2 p2 = __float22half2_rn(make_float2(softplusf(acc[4]), softplusf(acc[5])));
    __half2 p3 = __float22half2_rn(make_float2(softplusf(acc[6]), softplusf(acc[7])));
    uint4 st;
    st.x = *(uint32_t*)&p0;
    st.y = *(uint32_t*)&p1;
    st.z = *(uint32_t*)&p2;
    st.w = *(uint32_t*)&p3;
    *(uint4*)outp = st;
}

// ---------------- aggregation layer 2 + epilogue: fp16 gather, 16 lanes/node ----------------
__global__ void __launch_bounds__(256)
k_agg2(float* __restrict__ out) {
    int node = blockIdx.x * 16 + (threadIdx.x >> 4);
    int lane = threadIdx.x & 15;
    const __half* H = d_HAh;   // reused, stride HD2P halves
    float di = d_dinv[node];
    float sw = di * di;

    const int coff = lane * 8;
    const __half* srow = H + (size_t)node * HD2P;
    float acc[8];
    {
        uint4 u = *(const uint4*)(srow + coff);
        const __half2* h2 = (const __half2*)&u;
#pragma unroll
        for (int j = 0; j < 4; j++) {
            float2 f = __half22float2(h2[j]);
            acc[2 * j] = f.x * sw;
            acc[2 * j + 1] = f.y * sw;
        }
    }
    float acck = (lane == 0) ? __half2float(srow[128]) * sw : 0.0f;

    int e = d_rp[node], e1 = d_rp[node + 1];
    for (; e + 3 < e1; e += 4) {
        int s0 = d_col[e], s1 = d_col[e + 1], s2 = d_col[e + 2], s3 = d_col[e + 3];
        float w0 = di * d_dinv[s0];
        float w1 = di * d_dinv[s1];
        float w2 = di * d_dinv[s2];
        float w3 = di * d_dinv[s3];
        const __half* r0 = H + (size_t)s0 * HD2P;
        const __half* r1 = H + (size_t)s1 * HD2P;
        const __half* r2 = H + (size_t)s2 * HD2P;
        const __half* r3 = H + (size_t)s3 * HD2P;
        uint4 u0 = *(const uint4*)(r0 + coff);
        uint4 u1 = *(const uint4*)(r1 + coff);
        uint4 u2 = *(const uint4*)(r2 + coff);
        uint4 u3 = *(const uint4*)(r3 + coff);
        const __half2* a0 = (const __half2*)&u0;
        const __half2* a1 = (const __half2*)&u1;
        const __half2* a2 = (const __half2*)&u2;
        const __half2* a3 = (const __half2*)&u3;
#pragma unroll
        for (int j = 0; j < 4; j++) {
            float2 f0 = __half22float2(a0[j]);
            float2 f1 = __half22float2(a1[j]);
            float2 f2 = __half22float2(a2[j]);
            float2 f3 = __half22float2(a3[j]);
            acc[2 * j]     += f0.x * w0 + f1.x * w1 + f2.x * w2 + f3.x * w3;
            acc[2 * j + 1] += f0.y * w0 + f1.y * w1 + f2.y * w2 + f3.y * w3;
        }
        if (lane == 0)
            acck += __half2float(r0[128]) * w0 + __half2float(r1[128]) * w1
                  + __half2float(r2[128]) * w2 + __half2float(r3[128]) * w3;
    }
    for (; e < e1; e++) {
        int s0 = d_col[e];
        float w0 = di * d_dinv[s0];
        const __half* r0 = H + (size_t)s0 * HD2P;
        uint4 u0 = *(const uint4*)(r0 + coff);
        const __half2* a0 = (const __half2*)&u0;
#pragma unroll
        for (int j = 0; j < 4; j++) {
            float2 f0 = __half22float2(a0[j]);
            acc[2 * j]     += f0.x * w0;
            acc[2 * j + 1] += f0.y * w0;
        }
        if (lane == 0) acck += __half2float(r0[128]) * w0;
    }

    float lbd[8];
#pragma unroll
    for (int j = 0; j < 8; j++) lbd[j] = softplusf(acc[j]);

    float g = 0.0f, kap = 0.0f;
    if (lane == 0) {
        kap = softplusf(acck) + 0.1f;
        g = expf(lgammaf(1.0f + 1.0f / kap));
    }
    g = __shfl_sync(0xffffffffu, g, (threadIdx.x & 16), 32);

    const size_t ZOFF = 0;
    const size_t LOFF = (size_t)NN * 128;
    const size_t KOFF = (size_t)NN * 256;

    float* zp = out + ZOFF + (size_t)node * 128 + coff;
    float* lp = out + LOFF + (size_t)node * 128 + coff;
    *(float4*)zp       = make_float4(lbd[0] * g, lbd[1] * g, lbd[2] * g, lbd[3] * g);
    *(float4*)(zp + 4) = make_float4(lbd[4] * g, lbd[5] * g, lbd[6] * g, lbd[7] * g);
    *(float4*)lp       = make_float4(lbd[0], lbd[1], lbd[2], lbd[3]);
    *(float4*)(lp + 4) = make_float4(lbd[4], lbd[5], lbd[6], lbd[7]);
    if (lane == 0) out[KOFF + node] = kap;
}

// ---------------- launch ----------------
extern "C" void kernel_launch(void* const* d_in, const int* in_sizes, int n_in,
                              void* d_out, int out_size) {
    const float* x  = (const float*)d_in[0];
    const int* eidx = (const int*)d_in[1];
    const float* W0 = (const float*)d_in[2];
    const float* W1 = (const float*)d_in[3];
    float* out = (float*)d_out;

    const int4* src4 = (const int4*)eidx;
    const int4* dst4 = (const int4*)(eidx + NE);

    __half* HAh; cudaGetSymbolAddress((void**)&HAh, d_HAh);
    __half* HB;  cudaGetSymbolAddress((void**)&HB, d_HB);
    float* W1p;  cudaGetSymbolAddress((void**)&W1p, d_W1p);

    // Side stream + events (capture-legal fork/join, proven R6/R7).
    cudaStream_t s1;
    cudaStreamCreateWithFlags(&s1, cudaStreamNonBlocking);
    cudaEvent_t ef, ej, ea0, eg0;
    cudaEventCreateWithFlags(&ef, cudaEventDisableTiming);
    cudaEventCreateWithFlags(&ej, cudaEventDisableTiming);
    cudaEventCreateWithFlags(&ea0, cudaEventDisableTiming);
    cudaEventCreateWithFlags(&eg0, cudaEventDisableTiming);

    cudaEventRecord(ef, 0);
    cudaStreamWaitEvent(s1, ef, 0);

    // CSR build on side stream (overlaps GEMM1)
    k_init<<<(INIT_N + 255) / 256, 256, 0, s1>>>(W1);
    k_hist<<<(NE / 4 + 255) / 256, 256, 0, s1>>>(dst4);
    k_blocksum<<<NBLK, SCAN_B, 0, s1>>>();
    k_bscan<<<1, 128, 0, s1>>>();
    k_local<<<NBLK, SCAN_B, 0, s1>>>();
    k_fill<<<(NE / 4 + 255) / 256, 256, 0, s1>>>(src4, dst4);
    cudaEventRecord(ej, s1);

    // GEMM1 on main stream: HAh(fp16) = x @ W0  (50000x256, K=512), BN=128
    {
        dim3 grid(2, (NN + 127) / 128);
        k_gemm_f16<false, true, 128><<<grid, 256>>>(x, W0, HAh, NN, HD1, INDIM,
                                                    INDIM, HD1, HD1);
    }

    // join: agg1 needs both GEMM1 and CSR
    cudaStreamWaitEvent(0, ej, 0);

    // ---- pipelined agg1 -> GEMM2 over node halves ----
    // agg1 first half on main
    k_agg1<<<NHALF / 8, 256>>>(0);
    cudaEventRecord(ea0, 0);

    // GEMM2 first half on side stream (overlaps agg1 second half), BN=64
    cudaStreamWaitEvent(s1, ea0, 0);
    {
        dim3 grid(3, (NHALF + 127) / 128);
        k_gemm_f16<true, true, 64><<<grid, 256, 0, s1>>>(
            HB, W1p, HAh, NHALF, HD2P, HD1, HD1, HD2P, HD2P);
    }
    cudaEventRecord(eg0, s1);

    // agg1 second half + GEMM2 second half on main
    k_agg1<<<(NN - NHALF) / 8, 256>>>(NHALF);
    {
        dim3 grid(3, (NN - NHALF + 127) / 128);
        k_gemm_f16<true, true, 64><<<grid, 256>>>(
            HB + (size_t)NHALF * HD1, W1p, HAh + (size_t)NHALF * HD2P,
            NN - NHALF, HD2P, HD1, HD1, HD2P, HD2P);
    }
    cudaStreamWaitEvent(0, eg0, 0);

    // AGG2 + softplus + Weibull epilogue -> out
    k_agg2<<<NN / 16, 256>>>(out);
}

// round 9
// speedup vs baseline: 3.0716x; 1.0469x over previous
#include <cuda_runtime.h>
#include <cuda_fp16.h>
#include <math.h>
#include <stdint.h>

// Problem constants
#define NN    50000
#define NE    1600000
#define INDIM 512
#define HD1   256
#define HD2R  129     // real cols of layer 2
#define HD2P  136     // padded stride in halves (272B, 16B-aligned)

#define SCAN_B 512
#define NBLK   ((NN + SCAN_B - 1) / SCAN_B)   // 98

// init kernel must cover BOTH d_cnt[NN] and d_W1p[HD1*HD2P]
#define INIT_N ((NN) > (HD1 * HD2P) ? (NN) : (HD1 * HD2P))

// ---------------- static scratch (no allocations allowed) ----------------
__device__ __half d_HAh[(size_t)NN * HD1];  // fp16 XW0; reused as fp16 H1W1 (stride HD2P)
__device__ __half d_HB[(size_t)NN * HD1];   // fp16 softplus(agg1)
__device__ int    d_col[NE];
__device__ int    d_rp[NN + 1];
__device__ int    d_cur[NN];
__device__ int    d_cnt[NN];
__device__ float  d_dinv[NN];
__device__ float  d_W1p[HD1 * HD2P];
__device__ int    d_bsum[NBLK];
__device__ int    d_boff[NBLK];

// ---------------- helpers ----------------
__device__ __forceinline__ float softplusf(float x) {
    return fmaxf(x, 0.0f) + log1pf(expf(-fabsf(x)));
}

__device__ __forceinline__ void mma_f16(float c[4], const uint32_t a[4],
                                        uint32_t b0, uint32_t b1) {
    asm volatile(
        "mma.sync.aligned.m16n8k16.row.col.f32.f16.f16.f32 "
        "{%0,%1,%2,%3}, {%4,%5,%6,%7}, {%8,%9}, {%0,%1,%2,%3};\n"
        : "+f"(c[0]), "+f"(c[1]), "+f"(c[2]), "+f"(c[3])
        : "r"(a[0]), "r"(a[1]), "r"(a[2]), "r"(a[3]), "r"(b0), "r"(b1));
}

// ---------------- init: zero cnt + pad W1 (grid covers INIT_N) ----------------
__global__ void k_init(const float* __restrict__ W1) {
    int i = blockIdx.x * blockDim.x + threadIdx.x;
    if (i < NN) d_cnt[i] = 0;
    if (i < HD1 * HD2P) {
        int k = i / HD2P, n = i % HD2P;
        d_W1p[i] = (n < HD2R) ? W1[k * HD2R + n] : 0.0f;
    }
}

// 4 edges per thread, vectorized index load
__global__ void k_hist(const int4* __restrict__ dst4) {
    int e = blockIdx.x * blockDim.x + threadIdx.x;
    if (e < NE / 4) {
        int4 d = dst4[e];
        atomicAdd(&d_cnt[d.x], 1);
        atomicAdd(&d_cnt[d.y], 1);
        atomicAdd(&d_cnt[d.z], 1);
        atomicAdd(&d_cnt[d.w], 1);
    }
}

// ---------------- parallel scan: block sums -> 1-block scan -> local scan ----------------
__global__ void k_blocksum() {
    __shared__ int sh[SCAN_B];
    int t = threadIdx.x;
    int i = blockIdx.x * SCAN_B + t;
    sh[t] = (i < NN) ? d_cnt[i] : 0;
    __syncthreads();
    for (int off = SCAN_B / 2; off > 0; off >>= 1) {
        if (t < off) sh[t] += sh[t + off];
        __syncthreads();
    }
    if (t == 0) d_bsum[blockIdx.x] = sh[0];
}

__global__ void k_bscan() {
    __shared__ int sh[128];
    int t = threadIdx.x;
    int v = (t < NBLK) ? d_bsum[t] : 0;
    sh[t] = v;
    __syncthreads();
    for (int off = 1; off < 128; off <<= 1) {
        int add = (t >= off) ? sh[t - off] : 0;
        __syncthreads();
        sh[t] += add;
        __syncthreads();
    }
    if (t < NBLK) d_boff[t] = sh[t] - v;   // exclusive
}

__global__ void k_local() {
    __shared__ int sh[SCAN_B];
    int t = threadIdx.x;
    int i = blockIdx.x * SCAN_B + t;
    int v = (i < NN) ? d_cnt[i] : 0;
    sh[t] = v;
    __syncthreads();
    for (int off = 1; off < SCAN_B; off <<= 1) {
        int add = (t >= off) ? sh[t - off] : 0;
        __syncthreads();
        sh[t] += add;
        __syncthreads();
    }
    if (i < NN) {
        int incl = sh[t];
        int base = d_boff[blockIdx.x] + incl - v;
        d_rp[i] = base;
        d_cur[i] = base;
        d_dinv[i] = rsqrtf((float)v + 1.0f);
        if (i == NN - 1) d_rp[NN] = d_boff[blockIdx.x] + incl;
    }
}

__global__ void k_fill(const int4* __restrict__ src4, const int4* __restrict__ dst4) {
    int e = blockIdx.x * blockDim.x + threadIdx.x;
    if (e >= NE / 4) return;
    int4 s = src4[e];
    int4 d = dst4[e];
    d_col[atomicAdd(&d_cur[d.x], 1)] = s.x;
    d_col[atomicAdd(&d_cur[d.y], 1)] = s.y;
    d_col[atomicAdd(&d_cur[d.z], 1)] = s.z;
    d_col[atomicAdd(&d_cur[d.w], 1)] = s.w;
}

// ---------------- fp16 tensor-core GEMM: 128xBN tile, BK=32, 256 threads ----------------
// A: fp32 (A_HALF=false) or fp16 (A_HALF=true) row-major MxK
// B: fp32 row-major KxN (converted to fp16 in smem)
// C: fp16 (OUT_HALF) or fp32.  BN in {64, 128}.
template <bool A_HALF, bool OUT_HALF, int BN>
__global__ void __launch_bounds__(256, 1)
k_gemm_f16(const void* __restrict__ Av, const float* __restrict__ Bg,
           void* __restrict__ Cv, int M, int N, int K,
           int lda, int ldb, int ldc) {
    constexpr int NT = BN / 32;      // n-tiles (8 cols) per warp
    constexpr int SA = 40;           // A smem stride (halves) -> conflict-free LDSM
    constexpr int SB = BN + 8;       // B smem stride (halves) -> conflict-free LDSM
    constexpr int LB = BN / 32;      // B float4 loads per thread per tile
    constexpr int BNQ = BN / 4;      // B float4s per k-row
    __shared__ __half As[128 * SA];
    __shared__ __half Bs[32 * SB];

    const int tid = threadIdx.x;
    const int warp = tid >> 5, lane = tid & 31;
    const int wm = warp >> 2, wn = warp & 3;
    const int g = lane >> 2, t = lane & 3;
    const int bm = blockIdx.y * 128, bn = blockIdx.x * BN;

    const int l8 = lane & 7;
    const int lm8 = (lane >> 3) & 1;
    const int lk8 = lane >> 4;
    const int arow_off = l8 + (lm8 << 3);

    const uint32_t as_base = (uint32_t)__cvta_generic_to_shared(As);
    const uint32_t bs_base = (uint32_t)__cvta_generic_to_shared(Bs);

    float acc[4][NT][4];
#pragma unroll
    for (int mt = 0; mt < 4; mt++)
#pragma unroll
        for (int nt = 0; nt < NT; nt++)
#pragma unroll
            for (int j = 0; j < 4; j++) acc[mt][nt][j] = 0.0f;

    uint4  raH[2];
    float4 raF[4];
    float4 rbF[LB];

    auto loadA = [&](int k0) {
        if (A_HALF) {
            const __half* A = (const __half*)Av;
#pragma unroll
            for (int i = 0; i < 2; i++) {
                int idx = tid + 256 * i;
                int r = idx >> 2, c = (idx & 3) << 3;
                int gr = bm + r;
                uint4 v = make_uint4(0u, 0u, 0u, 0u);
                if (gr < M) v = *(const uint4*)(A + (size_t)gr * lda + k0 + c);
                raH[i] = v;
            }
        } else {
            const float* A = (const float*)Av;
#pragma unroll
            for (int i = 0; i < 4; i++) {
                int idx = tid + 256 * i;
                int r = idx >> 3, c = (idx & 7) << 2;
                int gr = bm + r;
                float4 v = make_float4(0.f, 0.f, 0.f, 0.f);
                if (gr < M) v = *(const float4*)(A + (size_t)gr * lda + k0 + c);
                raF[i] = v;
            }
        }
    };
    auto loadB = [&](int k0) {
#pragma unroll
        for (int i = 0; i < LB; i++) {
            int idx = tid + 256 * i;
            int kr = idx / BNQ, c = (idx % BNQ) << 2;
            int gc = bn + c;
            float4 v = make_float4(0.f, 0.f, 0.f, 0.f);
            if (gc < N) v = *(const float4*)(Bg + (size_t)(k0 + kr) * ldb + gc);
            rbF[i] = v;
        }
    };
    auto storeA = [&]() {
        if (A_HALF) {
#pragma unroll
            for (int i = 0; i < 2; i++) {
                int idx = tid + 256 * i;
                int r = idx >> 2, c = (idx & 3) << 3;
                *(uint4*)&As[r * SA + c] = raH[i];
            }
        } else {
#pragma unroll
            for (int i = 0; i < 4; i++) {
                int idx = tid + 256 * i;
                int r = idx >> 3, c = (idx & 7) << 2;
                __half2 h0 = __float22half2_rn(make_float2(raF[i].x, raF[i].y));
                __half2 h1 = __float22half2_rn(make_float2(raF[i].z, raF[i].w));
                uint2 u;
                u.x = *(uint32_t*)&h0;
                u.y = *(uint32_t*)&h1;
                *(uint2*)&As[r * SA + c] = u;
            }
        }
    };
    auto storeB = [&]() {
#pragma unroll
        for (int i = 0; i < LB; i++) {
            int idx = tid + 256 * i;
            int kr = idx / BNQ, c = (idx % BNQ) << 2;
            __half2 h0 = __float22half2_rn(make_float2(rbF[i].x, rbF[i].y));
            __half2 h1 = __float22half2_rn(make_float2(rbF[i].z, rbF[i].w));
            uint2 u;
            u.x = *(uint32_t*)&h0;
            u.y = *(uint32_t*)&h1;
            *(uint2*)&Bs[kr * SB + c] = u;
        }
    };

    loadA(0); loadB(0); storeA(); storeB();
    __syncthreads();

    const int nIter = K >> 5;
    for (int it = 0; it < nIter; it++) {
        if (it + 1 < nIter) { loadA((it + 1) << 5); loadB((it + 1) << 5); }
#pragma unroll
        for (int kk = 0; kk < 2; kk++) {
            uint32_t a[4][4], b[NT / 2][4];
            const int acol = (kk << 4) + (lk8 << 3);
#pragma unroll
            for (int mt = 0; mt < 4; mt++) {
                int row = wm * 64 + mt * 16 + arow_off;
                uint32_t addr = as_base + (uint32_t)(row * SA + acol) * 2u;
                asm volatile(
                    "ldmatrix.sync.aligned.m8n8.x4.shared.b16 {%0,%1,%2,%3}, [%4];"
                    : "=r"(a[mt][0]), "=r"(a[mt][1]), "=r"(a[mt][2]), "=r"(a[mt][3])
                    : "r"(addr));
            }
            const int brow = (kk << 4) + arow_off;
#pragma unroll
            for (int h = 0; h < NT / 2; h++) {
                int ncol = wn * (NT * 8) + (h << 4) + (lk8 << 3);
                uint32_t addr = bs_base + (uint32_t)(brow * SB + ncol) * 2u;
                asm volatile(
                    "ldmatrix.sync.aligned.m8n8.x4.trans.shared.b16 {%0,%1,%2,%3}, [%4];"
                    : "=r"(b[h][0]), "=r"(b[h][1]), "=r"(b[h][2]), "=r"(b[h][3])
                    : "r"(addr));
            }
#pragma unroll
            for (int mt = 0; mt < 4; mt++)
#pragma unroll
                for (int nt = 0; nt < NT; nt++)
                    mma_f16(acc[mt][nt], a[mt],
                            b[nt >> 1][(nt & 1) * 2], b[nt >> 1][(nt & 1) * 2 + 1]);
        }
        __syncthreads();
        if (it + 1 < nIter) {
            storeA(); storeB();
            __syncthreads();
        }
    }

    // epilogue
#pragma unroll
    for (int mt = 0; mt < 4; mt++) {
        int r0 = bm + wm * 64 + mt * 16 + g;
        int r1 = r0 + 8;
#pragma unroll
        for (int nt = 0; nt < NT; nt++) {
            int c = bn + wn * (NT * 8) + nt * 8 + t * 2;
            if (c < N) {
                if (OUT_HALF) {
                    __half* C = (__half*)Cv;
                    if (r0 < M)
                        *(__half2*)(C + (size_t)r0 * ldc + c) =
                            __float22half2_rn(make_float2(acc[mt][nt][0], acc[mt][nt][1]));
                    if (r1 < M)
                        *(__half2*)(C + (size_t)r1 * ldc + c) =
                            __float22half2_rn(make_float2(acc[mt][nt][2], acc[mt][nt][3]));
                } else {
                    float* C = (float*)Cv;
                    if (r0 < M)
                        *(float2*)(C + (size_t)r0 * ldc + c) =
                            make_float2(acc[mt][nt][0], acc[mt][nt][1]);
                    if (r1 < M)
                        *(float2*)(C + (size_t)r1 * ldc + c) =
                            make_float2(acc[mt][nt][2], acc[mt][nt][3]);
                }
            }
        }
    }
}

// ---------------- aggregation layer 1: fp16 gather, 32 lanes/node -> fp16 out ----------------
__global__ void __launch_bounds__(256)
k_agg1() {
    int node = blockIdx.x * 8 + (threadIdx.x >> 5);
    int lane = threadIdx.x & 31;
    const __half* H = d_HAh;
    float di = d_dinv[node];
    float sw = di * di;

    const int coff = lane * 8;
    float acc[8];
    {
        uint4 u = *(const uint4*)(H + (size_t)node * HD1 + coff);
        const __half2* h2 = (const __half2*)&u;
#pragma unroll
        for (int j = 0; j < 4; j++) {
            float2 f = __half22float2(h2[j]);
            acc[2 * j] = f.x * sw;
            acc[2 * j + 1] = f.y * sw;
        }
    }

    int e = d_rp[node], e1 = d_rp[node + 1];
    // peel to 16B alignment of &d_col[e]
    while (e < e1 && (e & 3)) {
        int s0 = d_col[e];
        float w0 = di * d_dinv[s0];
        uint4 u0 = *(const uint4*)(H + (size_t)s0 * HD1 + coff);
        const __half2* a0 = (const __half2*)&u0;
#pragma unroll
        for (int j = 0; j < 4; j++) {
            float2 f0 = __half22float2(a0[j]);
            acc[2 * j]     += f0.x * w0;
            acc[2 * j + 1] += f0.y * w0;
        }
        e++;
    }
    for (; e + 3 < e1; e += 4) {
        int4 cc = *(const int4*)&d_col[e];   // one aligned 16B broadcast load
        float w0 = di * d_dinv[cc.x];
        float w1 = di * d_dinv[cc.y];
        float w2 = di * d_dinv[cc.z];
        float w3 = di * d_dinv[cc.w];
        uint4 u0 = *(const uint4*)(H + (size_t)cc.x * HD1 + coff);
        uint4 u1 = *(const uint4*)(H + (size_t)cc.y * HD1 + coff);
        uint4 u2 = *(const uint4*)(H + (size_t)cc.z * HD1 + coff);
        uint4 u3 = *(const uint4*)(H + (size_t)cc.w * HD1 + coff);
        const __half2* a0 = (const __half2*)&u0;
        const __half2* a1 = (const __half2*)&u1;
        const __half2* a2 = (const __half2*)&u2;
        const __half2* a3 = (const __half2*)&u3;
#pragma unroll
        for (int j = 0; j < 4; j++) {
            float2 f0 = __half22float2(a0[j]);
            float2 f1 = __half22float2(a1[j]);
            float2 f2 = __half22float2(a2[j]);
            float2 f3 = __half22float2(a3[j]);
            acc[2 * j]     += f0.x * w0 + f1.x * w1 + f2.x * w2 + f3.x * w3;
            acc[2 * j + 1] += f0.y * w0 + f1.y * w1 + f2.y * w2 + f3.y * w3;
        }
    }
    for (; e < e1; e++) {
        int s0 = d_col[e];
        float w0 = di * d_dinv[s0];
        uint4 u0 = *(const uint4*)(H + (size_t)s0 * HD1 + coff);
        const __half2* a0 = (const __half2*)&u0;
#pragma unroll
        for (int j = 0; j < 4; j++) {
            float2 f0 = __half22float2(a0[j]);
            acc[2 * j]     += f0.x * w0;
            acc[2 * j + 1] += f0.y * w0;
        }
    }

    __half* outp = d_HB + (size_t)node * HD1 + coff;
    __half2 p0 = __float22half2_rn(make_float2(softplusf(acc[0]), softplusf(acc[1])));
    __half2 p1 = __float22half2_rn(make_float2(softplusf(acc[2]), softplusf(acc[3])));
    __half2 p2 = __float22half2_rn(make_float2(softplusf(acc[4]), softplusf(acc[5])));
    __half2 p3 = __float22half2_rn(make_float2(softplusf(acc[6]), softplusf(acc[7])));
    uint4 st;
    st.x = *(uint32_t*)&p0;
    st.y = *(uint32_t*)&p1;
    st.z = *(uint32_t*)&p2;
    st.w = *(uint32_t*)&p3;
    *(uint4*)outp = st;
}

// ---------------- aggregation layer 2 + epilogue: fp16 gather, 16 lanes/node ----------------
__global__ void __launch_bounds__(256)
k_agg2(float* __restrict__ out) {
    int node = blockIdx.x * 16 + (threadIdx.x >> 4);
    int lane = threadIdx.x & 15;
    const __half* H = d_HAh;   // reused, stride HD2P halves
    float di = d_dinv[node];
    float sw = di * di;

    const int coff = lane * 8;
    const __half* srow = H + (size_t)node * HD2P;
    float acc[8];
    {
        uint4 u = *(const uint4*)(srow + coff);
        const __half2* h2 = (const __half2*)&u;
#pragma unroll
        for (int j = 0; j < 4; j++) {
            float2 f = __half22float2(h2[j]);
            acc[2 * j] = f.x * sw;
            acc[2 * j + 1] = f.y * sw;
        }
    }
    float acck = (lane == 0) ? __half2float(srow[128]) * sw : 0.0f;

    int e = d_rp[node], e1 = d_rp[node + 1];
    for (; e + 3 < e1; e += 4) {
        int s0 = d_col[e], s1 = d_col[e + 1], s2 = d_col[e + 2], s3 = d_col[e + 3];
        float w0 = di * d_dinv[s0];
        float w1 = di * d_dinv[s1];
        float w2 = di * d_dinv[s2];
        float w3 = di * d_dinv[s3];
        const __half* r0 = H + (size_t)s0 * HD2P;
        const __half* r1 = H + (size_t)s1 * HD2P;
        const __half* r2 = H + (size_t)s2 * HD2P;
        const __half* r3 = H + (size_t)s3 * HD2P;
        uint4 u0 = *(const uint4*)(r0 + coff);
        uint4 u1 = *(const uint4*)(r1 + coff);
        uint4 u2 = *(const uint4*)(r2 + coff);
        uint4 u3 = *(const uint4*)(r3 + coff);
        const __half2* a0 = (const __half2*)&u0;
        const __half2* a1 = (const __half2*)&u1;
        const __half2* a2 = (const __half2*)&u2;
        const __half2* a3 = (const __half2*)&u3;
#pragma unroll
        for (int j = 0; j < 4; j++) {
            float2 f0 = __half22float2(a0[j]);
            float2 f1 = __half22float2(a1[j]);
            float2 f2 = __half22float2(a2[j]);
            float2 f3 = __half22float2(a3[j]);
            acc[2 * j]     += f0.x * w0 + f1.x * w1 + f2.x * w2 + f3.x * w3;
            acc[2 * j + 1] += f0.y * w0 + f1.y * w1 + f2.y * w2 + f3.y * w3;
        }
        if (lane == 0)
            acck += __half2float(r0[128]) * w0 + __half2float(r1[128]) * w1
                  + __half2float(r2[128]) * w2 + __half2float(r3[128]) * w3;
    }
    for (; e < e1; e++) {
        int s0 = d_col[e];
        float w0 = di * d_dinv[s0];
        const __half* r0 = H + (size_t)s0 * HD2P;
        uint4 u0 = *(const uint4*)(r0 + coff);
        const __half2* a0 = (const __half2*)&u0;
#pragma unroll
        for (int j = 0; j < 4; j++) {
            float2 f0 = __half22float2(a0[j]);
            acc[2 * j]     += f0.x * w0;
            acc[2 * j + 1] += f0.y * w0;
        }
        if (lane == 0) acck += __half2float(r0[128]) * w0;
    }

    float lbd[8];
#pragma unroll
    for (int j = 0; j < 8; j++) lbd[j] = softplusf(acc[j]);

    float g = 0.0f, kap = 0.0f;
    if (lane == 0) {
        kap = softplusf(acck) + 0.1f;
        g = expf(lgammaf(1.0f + 1.0f / kap));
    }
    g = __shfl_sync(0xffffffffu, g, (threadIdx.x & 16), 32);

    const size_t ZOFF = 0;
    const size_t LOFF = (size_t)NN * 128;
    const size_t KOFF = (size_t)NN * 256;

    float* zp = out + ZOFF + (size_t)node * 128 + coff;
    float* lp = out + LOFF + (size_t)node * 128 + coff;
    *(float4*)zp       = make_float4(lbd[0] * g, lbd[1] * g, lbd[2] * g, lbd[3] * g);
    *(float4*)(zp + 4) = make_float4(lbd[4] * g, lbd[5] * g, lbd[6] * g, lbd[7] * g);
    *(float4*)lp       = make_float4(lbd[0], lbd[1], lbd[2], lbd[3]);
    *(float4*)(lp + 4) = make_float4(lbd[4], lbd[5], lbd[6], lbd[7]);
    if (lane == 0) out[KOFF + node] = kap;
}

// ---------------- launch ----------------
extern "C" void kernel_launch(void* const* d_in, const int* in_sizes, int n_in,
                              void* d_out, int out_size) {
    const float* x  = (const float*)d_in[0];
    const int* eidx = (const int*)d_in[1];
    const float* W0 = (const float*)d_in[2];
    const float* W1 = (const float*)d_in[3];
    float* out = (float*)d_out;

    const int4* src4 = (const int4*)eidx;
    const int4* dst4 = (const int4*)(eidx + NE);

    __half* HAh; cudaGetSymbolAddress((void**)&HAh, d_HAh);
    __half* HB;  cudaGetSymbolAddress((void**)&HB, d_HB);
    float* W1p;  cudaGetSymbolAddress((void**)&W1p, d_W1p);

    // Side stream + events (capture-legal fork/join, proven R6-R8).
    cudaStream_t s1;
    cudaStreamCreateWithFlags(&s1, cudaStreamNonBlocking);
    cudaEvent_t ef, ej;
    cudaEventCreateWithFlags(&ef, cudaEventDisableTiming);
    cudaEventCreateWithFlags(&ej, cudaEventDisableTiming);

    cudaEventRecord(ef, 0);
    cudaStreamWaitEvent(s1, ef, 0);

    // CSR build (part 1) on side stream — submission indices 0,1,2
    k_init<<<(INIT_N + 255) / 256, 256, 0, s1>>>(W1);
    k_hist<<<(NE / 4 + 255) / 256, 256, 0, s1>>>(dst4);
    k_blocksum<<<NBLK, SCAN_B, 0, s1>>>();

    // GEMM1 on main stream — submission index 3 (ncu capture slot):
    // HAh(fp16) = x @ W0  (50000x256, K=512), BN=128
    {
        dim3 grid(2, (NN + 127) / 128);
        k_gemm_f16<false, true, 128><<<grid, 256>>>(x, W0, HAh, NN, HD1, INDIM,
                                                    INDIM, HD1, HD1);
    }

    // CSR build (part 2) on side stream — overlaps GEMM1
    k_bscan<<<1, 128, 0, s1>>>();
    k_local<<<NBLK, SCAN_B, 0, s1>>>();
    k_fill<<<(NE / 4 + 255) / 256, 256, 0, s1>>>(src4, dst4);
    cudaEventRecord(ej, s1);

    // join: agg1 needs both GEMM1 and CSR
    cudaStreamWaitEvent(0, ej, 0);

    // AGG1 + softplus -> HB (fp16)
    k_agg1<<<NN / 8, 256>>>();
    // GEMM2: HAh(fp16, stride 136) = HB(fp16) @ W1p  (50000x136, K=256), BN=64
    {
        dim3 grid(3, (NN + 127) / 128);
        k_gemm_f16<true, true, 64><<<grid, 256>>>(HB, W1p, HAh, NN, HD2P, HD1,
                                                  HD1, HD2P, HD2P);
    }
    // AGG2 + softplus + Weibull epilogue -> out
    k_agg2<<<NN / 16, 256>>>(out);
}

// round 10
// speedup vs baseline: 3.3602x; 1.0939x over previous
#include <cuda_runtime.h>
#include <cuda_fp16.h>
#include <math.h>
#include <stdint.h>

// Problem constants
#define NN    50000
#define NE    1600000
#define INDIM 512
#define HD1   256
#define HD2R  129     // real cols of layer 2
#define HD2P  136     // padded stride in halves (272B, 16B-aligned)

#define SCAN_B 512
#define NBLK   ((NN + SCAN_B - 1) / SCAN_B)   // 98

#define INIT_N ((NN) > (HD1 * HD2P) ? (NN) : (HD1 * HD2P))
#define XCHUNKS (NN * INDIM / 8)        // 3,200,000 8-elem chunks
#define W0CHUNKS (INDIM * HD1 / 8)      // 16,384

// ---------------- static scratch (no allocations allowed) ----------------
__device__ __half d_Xh[(size_t)NN * INDIM];   // fp16 copy of x
__device__ __half d_W0h[INDIM * HD1];         // fp16 W0
__device__ __half d_W1h[HD1 * HD2P];          // fp16 W1, padded
__device__ __half d_HAh[(size_t)NN * HD1];    // fp16 XW0; reused as H1W1 (stride HD2P)
__device__ __half d_HB[(size_t)NN * HD1];     // fp16 softplus(agg1)
__device__ int    d_col[NE];
__device__ int    d_rp[NN + 1];
__device__ int    d_cur[NN];
__device__ int    d_cnt[NN];
__device__ float  d_dinv[NN];
__device__ int    d_bsum[NBLK];
__device__ int    d_boff[NBLK];

// ---------------- helpers ----------------
__device__ __forceinline__ float softplusf(float x) {
    return fmaxf(x, 0.0f) + log1pf(expf(-fabsf(x)));
}

__device__ __forceinline__ void mma_f16(float c[4], const uint32_t a[4],
                                        uint32_t b0, uint32_t b1) {
    asm volatile(
        "mma.sync.aligned.m16n8k16.row.col.f32.f16.f16.f32 "
        "{%0,%1,%2,%3}, {%4,%5,%6,%7}, {%8,%9}, {%0,%1,%2,%3};\n"
        : "+f"(c[0]), "+f"(c[1]), "+f"(c[2]), "+f"(c[3])
        : "r"(a[0]), "r"(a[1]), "r"(a[2]), "r"(a[3]), "r"(b0), "r"(b1));
}

__device__ __forceinline__ void cp_async16(uint32_t smem_dst, const void* gsrc, int src_bytes) {
    asm volatile("cp.async.cg.shared.global [%0], [%1], 16, %2;\n"
                 :: "r"(smem_dst), "l"(gsrc), "r"(src_bytes) : "memory");
}
__device__ __forceinline__ void cp_commit() {
    asm volatile("cp.async.commit_group;\n" ::: "memory");
}
template <int N>
__device__ __forceinline__ void cp_wait() {
    asm volatile("cp.async.wait_group %0;\n" :: "n"(N) : "memory");
}

__device__ __forceinline__ uint4 pack8(float4 f0, float4 f1) {
    __half2 h0 = __float22half2_rn(make_float2(f0.x, f0.y));
    __half2 h1 = __float22half2_rn(make_float2(f0.z, f0.w));
    __half2 h2 = __float22half2_rn(make_float2(f1.x, f1.y));
    __half2 h3 = __float22half2_rn(make_float2(f1.z, f1.w));
    uint4 u;
    u.x = *(uint32_t*)&h0; u.y = *(uint32_t*)&h1;
    u.z = *(uint32_t*)&h2; u.w = *(uint32_t*)&h3;
    return u;
}

// ---------------- fp32 -> fp16 conversion (x and W0) ----------------
__global__ void k_cvtx(const float* __restrict__ x, const float* __restrict__ W0) {
    int i = blockIdx.x * blockDim.x + threadIdx.x;
    if (i < XCHUNKS) {
        const float4* p = (const float4*)x + (size_t)i * 2;
        ((uint4*)d_Xh)[i] = pack8(p[0], p[1]);
    }
    if (i < W0CHUNKS) {
        const float4* p = (const float4*)W0 + (size_t)i * 2;
        ((uint4*)d_W0h)[i] = pack8(p[0], p[1]);
    }
}

// ---------------- init: zero cnt + pad/convert W1 ----------------
__global__ void k_init(const float* __restrict__ W1) {
    int i = blockIdx.x * blockDim.x + threadIdx.x;
    if (i < NN) d_cnt[i] = 0;
    if (i < HD1 * HD2P) {
        int k = i / HD2P, n = i % HD2P;
        d_W1h[i] = __float2half((n < HD2R) ? W1[k * HD2R + n] : 0.0f);
    }
}

__global__ void k_hist(const int4* __restrict__ dst4) {
    int e = blockIdx.x * blockDim.x + threadIdx.x;
    if (e < NE / 4) {
        int4 d = dst4[e];
        atomicAdd(&d_cnt[d.x], 1);
        atomicAdd(&d_cnt[d.y], 1);
        atomicAdd(&d_cnt[d.z], 1);
        atomicAdd(&d_cnt[d.w], 1);
    }
}

__global__ void k_blocksum() {
    __shared__ int sh[SCAN_B];
    int t = threadIdx.x;
    int i = blockIdx.x * SCAN_B + t;
    sh[t] = (i < NN) ? d_cnt[i] : 0;
    __syncthreads();
    for (int off = SCAN_B / 2; off > 0; off >>= 1) {
        if (t < off) sh[t] += sh[t + off];
        __syncthreads();
    }
    if (t == 0) d_bsum[blockIdx.x] = sh[0];
}

__global__ void k_bscan() {
    __shared__ int sh[128];
    int t = threadIdx.x;
    int v = (t < NBLK) ? d_bsum[t] : 0;
    sh[t] = v;
    __syncthreads();
    for (int off = 1; off < 128; off <<= 1) {
        int add = (t >= off) ? sh[t - off] : 0;
        __syncthreads();
        sh[t] += add;
        __syncthreads();
    }
    if (t < NBLK) d_boff[t] = sh[t] - v;
}

__global__ void k_local() {
    __shared__ int sh[SCAN_B];
    int t = threadIdx.x;
    int i = blockIdx.x * SCAN_B + t;
    int v = (i < NN) ? d_cnt[i] : 0;
    sh[t] = v;
    __syncthreads();
    for (int off = 1; off < SCAN_B; off <<= 1) {
        int add = (t >= off) ? sh[t - off] : 0;
        __syncthreads();
        sh[t] += add;
        __syncthreads();
    }
    if (i < NN) {
        int incl = sh[t];
        int base = d_boff[blockIdx.x] + incl - v;
        d_rp[i] = base;
        d_cur[i] = base;
        d_dinv[i] = rsqrtf((float)v + 1.0f);
        if (i == NN - 1) d_rp[NN] = d_boff[blockIdx.x] + incl;
    }
}

__global__ void k_fill(const int4* __restrict__ src4, const int4* __restrict__ dst4) {
    int e = blockIdx.x * blockDim.x + threadIdx.x;
    if (e >= NE / 4) return;
    int4 s = src4[e];
    int4 d = dst4[e];
    d_col[atomicAdd(&d_cur[d.x], 1)] = s.x;
    d_col[atomicAdd(&d_cur[d.y], 1)] = s.y;
    d_col[atomicAdd(&d_cur[d.z], 1)] = s.z;
    d_col[atomicAdd(&d_cur[d.w], 1)] = s.w;
}

// ---------------- cp.async fp16 GEMM: 128xBN tile, BK=32, 3 stages, 256 thr ----------
// A fp16 row-major MxK (lda), B fp16 row-major KxN (ldb), C fp16 row-major (ldc)
template <int BN>
__global__ void __launch_bounds__(256, 2)
k_gemm_cp(const __half* __restrict__ Ag, const __half* __restrict__ Bg,
          __half* __restrict__ Cg, int M, int N, int K,
          int lda, int ldb, int ldc) {
    constexpr int NT = BN / 32;              // n-tiles (8 cols) per warp
    constexpr int SA = 40;                   // A smem stride (halves)
    constexpr int SB = BN + 8;               // B smem stride (halves)
    constexpr int ASZ = 128 * SA * 2;        // bytes per A stage
    constexpr int BSZ = 32 * SB * 2;         // bytes per B stage
    constexpr int STAGES = 3;

    extern __shared__ char dsm[];

    const int tid = threadIdx.x;
    const int warp = tid >> 5, lane = tid & 31;
    const int wm = warp >> 2, wn = warp & 3;
    const int g = lane >> 2, t = lane & 3;
    const int bm = blockIdx.y * 128, bn = blockIdx.x * BN;

    const int l8 = lane & 7;
    const int lm8 = (lane >> 3) & 1;
    const int lk8 = lane >> 4;
    const int arow_off = l8 + (lm8 << 3);

    uint32_t sbase[STAGES];
#pragma unroll
    for (int s = 0; s < STAGES; s++)
        sbase[s] = (uint32_t)__cvta_generic_to_shared(dsm + s * (ASZ + BSZ));

    float acc[4][NT][4];
#pragma unroll
    for (int mt = 0; mt < 4; mt++)
#pragma unroll
        for (int nt = 0; nt < NT; nt++)
#pragma unroll
            for (int j = 0; j < 4; j++) acc[mt][nt][j] = 0.0f;

    const int nIter = K >> 5;

    auto issue = [&](int it) {
        const int k0 = it << 5;
        const uint32_t sa = sbase[it % STAGES];
        const uint32_t sb = sa + ASZ;
        // A: 128x32 halves = 512 16B chunks -> 2 per thread
#pragma unroll
        for (int i = 0; i < 2; i++) {
            int idx = tid + 256 * i;
            int r = idx >> 2, ch = (idx & 3) << 3;
            int gr = bm + r;
            int cr = (gr < M) ? gr : (M - 1);
            const __half* src = Ag + (size_t)cr * lda + k0 + ch;
            cp_async16(sa + (uint32_t)(r * SA + ch) * 2u, src, (gr < M) ? 16 : 0);
        }
        // B: 32xBN halves
        if (BN == 128) {
#pragma unroll
            for (int i = 0; i < 2; i++) {
                int idx = tid + 256 * i;
                int r = idx >> 4, ch = (idx & 15) << 3;
                int gc = bn + ch;
                int cc = (gc < N) ? gc : 0;
                const __half* src = Bg + (size_t)(k0 + r) * ldb + cc;
                cp_async16(sb + (uint32_t)(r * SB + ch) * 2u, src, (gc < N) ? 16 : 0);
            }
        } else {  // BN == 64: 256 chunks -> 1 per thread
            int r = tid >> 3, ch = (tid & 7) << 3;
            int gc = bn + ch;
            int cc = (gc < N) ? gc : 0;
            const __half* src = Bg + (size_t)(k0 + r) * ldb + cc;
            cp_async16(sb + (uint32_t)(r * SB + ch) * 2u, src, (gc < N) ? 16 : 0);
        }
        cp_commit();
    };

    issue(0);
    if (nIter > 1) issue(1); else cp_commit();

    for (int it = 0; it < nIter; it++) {
        cp_wait<1>();
        __syncthreads();
        if (it + 2 < nIter) issue(it + 2);

        const uint32_t as_b = sbase[it % STAGES];
        const uint32_t bs_b = as_b + ASZ;
#pragma unroll
        for (int kk = 0; kk < 2; kk++) {
            uint32_t a[4][4], b[NT / 2][4];
            const int acol = (kk << 4) + (lk8 << 3);
#pragma unroll
            for (int mt = 0; mt < 4; mt++) {
                int row = wm * 64 + mt * 16 + arow_off;
                uint32_t addr = as_b + (uint32_t)(row * SA + acol) * 2u;
                asm volatile(
                    "ldmatrix.sync.aligned.m8n8.x4.shared.b16 {%0,%1,%2,%3}, [%4];"
                    : "=r"(a[mt][0]), "=r"(a[mt][1]), "=r"(a[mt][2]), "=r"(a[mt][3])
                    : "r"(addr));
            }
            const int brow = (kk << 4) + arow_off;
#pragma unroll
            for (int h = 0; h < NT / 2; h++) {
                int ncol = wn * (NT * 8) + (h << 4) + (lk8 << 3);
                uint32_t addr = bs_b + (uint32_t)(brow * SB + ncol) * 2u;
                asm volatile(
                    "ldmatrix.sync.aligned.m8n8.x4.trans.shared.b16 {%0,%1,%2,%3}, [%4];"
                    : "=r"(b[h][0]), "=r"(b[h][1]), "=r"(b[h][2]), "=r"(b[h][3])
                    : "r"(addr));
            }
#pragma unroll
            for (int mt = 0; mt < 4; mt++)
#pragma unroll
                for (int nt = 0; nt < NT; nt++)
                    mma_f16(acc[mt][nt], a[mt],
                            b[nt >> 1][(nt & 1) * 2], b[nt >> 1][(nt & 1) * 2 + 1]);
        }
        __syncthreads();
    }

    // epilogue
#pragma unroll
    for (int mt = 0; mt < 4; mt++) {
        int r0 = bm + wm * 64 + mt * 16 + g;
        int r1 = r0 + 8;
#pragma unroll
        for (int nt = 0; nt < NT; nt++) {
            int c = bn + wn * (NT * 8) + nt * 8 + t * 2;
            if (c < N) {
                if (r0 < M)
                    *(__half2*)(Cg + (size_t)r0 * ldc + c) =
                        __float22half2_rn(make_float2(acc[mt][nt][0], acc[mt][nt][1]));
                if (r1 < M)
                    *(__half2*)(Cg + (size_t)r1 * ldc + c) =
                        __float22half2_rn(make_float2(acc[mt][nt][2], acc[mt][nt][3]));
            }
        }
    }
}

// ---------------- aggregation layer 1: fp16 gather, 32 lanes/node -> fp16 out ----------------
__global__ void __launch_bounds__(256)
k_agg1() {
    int node = blockIdx.x * 8 + (threadIdx.x >> 5);
    int lane = threadIdx.x & 31;
    const __half* H = d_HAh;
    float di = d_dinv[node];
    float sw = di * di;

    const int coff = lane * 8;
    float acc[8];
    {
        uint4 u = *(const uint4*)(H + (size_t)node * HD1 + coff);
        const __half2* h2 = (const __half2*)&u;
#pragma unroll
        for (int j = 0; j < 4; j++) {
            float2 f = __half22float2(h2[j]);
            acc[2 * j] = f.x * sw;
            acc[2 * j + 1] = f.y * sw;
        }
    }

    int e = d_rp[node], e1 = d_rp[node + 1];
    while (e < e1 && (e & 3)) {
        int s0 = d_col[e];
        float w0 = di * d_dinv[s0];
        uint4 u0 = *(const uint4*)(H + (size_t)s0 * HD1 + coff);
        const __half2* a0 = (const __half2*)&u0;
#pragma unroll
        for (int j = 0; j < 4; j++) {
            float2 f0 = __half22float2(a0[j]);
            acc[2 * j]     += f0.x * w0;
            acc[2 * j + 1] += f0.y * w0;
        }
        e++;
    }
    for (; e + 3 < e1; e += 4) {
        int4 cc = *(const int4*)&d_col[e];
        float w0 = di * d_dinv[cc.x];
        float w1 = di * d_dinv[cc.y];
        float w2 = di * d_dinv[cc.z];
        float w3 = di * d_dinv[cc.w];
        uint4 u0 = *(const uint4*)(H + (size_t)cc.x * HD1 + coff);
        uint4 u1 = *(const uint4*)(H + (size_t)cc.y * HD1 + coff);
        uint4 u2 = *(const uint4*)(H + (size_t)cc.z * HD1 + coff);
        uint4 u3 = *(const uint4*)(H + (size_t)cc.w * HD1 + coff);
        const __half2* a0 = (const __half2*)&u0;
        const __half2* a1 = (const __half2*)&u1;
        const __half2* a2 = (const __half2*)&u2;
        const __half2* a3 = (const __half2*)&u3;
#pragma unroll
        for (int j = 0; j < 4; j++) {
            float2 f0 = __half22float2(a0[j]);
            float2 f1 = __half22float2(a1[j]);
            float2 f2 = __half22float2(a2[j]);
            float2 f3 = __half22float2(a3[j]);
            acc[2 * j]     += f0.x * w0 + f1.x * w1 + f2.x * w2 + f3.x * w3;
            acc[2 * j + 1] += f0.y * w0 + f1.y * w1 + f2.y * w2 + f3.y * w3;
        }
    }
    for (; e < e1; e++) {
        int s0 = d_col[e];
        float w0 = di * d_dinv[s0];
        uint4 u0 = *(const uint4*)(H + (size_t)s0 * HD1 + coff);
        const __half2* a0 = (const __half2*)&u0;
#pragma unroll
        for (int j = 0; j < 4; j++) {
            float2 f0 = __half22float2(a0[j]);
            acc[2 * j]     += f0.x * w0;
            acc[2 * j + 1] += f0.y * w0;
        }
    }

    __half* outp = d_HB + (size_t)node * HD1 + coff;
    __half2 p0 = __float22half2_rn(make_float2(softplusf(acc[0]), softplusf(acc[1])));
    __half2 p1 = __float22half2_rn(make_float2(softplusf(acc[2]), softplusf(acc[3])));
    __half2 p2 = __float22half2_rn(make_float2(softplusf(acc[4]), softplusf(acc[5])));
    __half2 p3 = __float22half2_rn(make_float2(softplusf(acc[6]), softplusf(acc[7])));
    uint4 st;
    st.x = *(uint32_t*)&p0;
    st.y = *(uint32_t*)&p1;
    st.z = *(uint32_t*)&p2;
    st.w = *(uint32_t*)&p3;
    *(uint4*)outp = st;
}

// ---------------- aggregation layer 2 + epilogue: fp16 gather, 16 lanes/node ----------------
__global__ void __launch_bounds__(256)
k_agg2(float* __restrict__ out) {
    int node = blockIdx.x * 16 + (threadIdx.x >> 4);
    int lane = threadIdx.x & 15;
    const __half* H = d_HAh;
    float di = d_dinv[node];
    float sw = di * di;

    const int coff = lane * 8;
    const __half* srow = H + (size_t)node * HD2P;
    float acc[8];
    {
        uint4 u = *(const uint4*)(srow + coff);
        const __half2* h2 = (const __half2*)&u;
#pragma unroll
        for (int j = 0; j < 4; j++) {
            float2 f = __half22float2(h2[j]);
            acc[2 * j] = f.x * sw;
            acc[2 * j + 1] = f.y * sw;
        }
    }
    float acck = (lane == 0) ? __half2float(srow[128]) * sw : 0.0f;

    int e = d_rp[node], e1 = d_rp[node + 1];
    for (; e + 3 < e1; e += 4) {
        int s0 = d_col[e], s1 = d_col[e + 1], s2 = d_col[e + 2], s3 = d_col[e + 3];
        float w0 = di * d_dinv[s0];
        float w1 = di * d_dinv[s1];
        float w2 = di * d_dinv[s2];
        float w3 = di * d_dinv[s3];
        const __half* r0 = H + (size_t)s0 * HD2P;
        const __half* r1 = H + (size_t)s1 * HD2P;
        const __half* r2 = H + (size_t)s2 * HD2P;
        const __half* r3 = H + (size_t)s3 * HD2P;
        uint4 u0 = *(const uint4*)(r0 + coff);
        uint4 u1 = *(const uint4*)(r1 + coff);
        uint4 u2 = *(const uint4*)(r2 + coff);
        uint4 u3 = *(const uint4*)(r3 + coff);
        const __half2* a0 = (const __half2*)&u0;
        const __half2* a1 = (const __half2*)&u1;
        const __half2* a2 = (const __half2*)&u2;
        const __half2* a3 = (const __half2*)&u3;
#pragma unroll
        for (int j = 0; j < 4; j++) {
            float2 f0 = __half22float2(a0[j]);
            float2 f1 = __half22float2(a1[j]);
            float2 f2 = __half22float2(a2[j]);
            float2 f3 = __half22float2(a3[j]);
            acc[2 * j]     += f0.x * w0 + f1.x * w1 + f2.x * w2 + f3.x * w3;
            acc[2 * j + 1] += f0.y * w0 + f1.y * w1 + f2.y * w2 + f3.y * w3;
        }
        if (lane == 0)
            acck += __half2float(r0[128]) * w0 + __half2float(r1[128]) * w1
                  + __half2float(r2[128]) * w2 + __half2float(r3[128]) * w3;
    }
    for (; e < e1; e++) {
        int s0 = d_col[e];
        float w0 = di * d_dinv[s0];
        const __half* r0 = H + (size_t)s0 * HD2P;
        uint4 u0 = *(const uint4*)(r0 + coff);
        const __half2* a0 = (const __half2*)&u0;
#pragma unroll
        for (int j = 0; j < 4; j++) {
            float2 f0 = __half22float2(a0[j]);
            acc[2 * j]     += f0.x * w0;
            acc[2 * j + 1] += f0.y * w0;
        }
        if (lane == 0) acck += __half2float(r0[128]) * w0;
    }

    float lbd[8];
#pragma unroll
    for (int j = 0; j < 8; j++) lbd[j] = softplusf(acc[j]);

    float g = 0.0f, kap = 0.0f;
    if (lane == 0) {
        kap = softplusf(acck) + 0.1f;
        g = expf(lgammaf(1.0f + 1.0f / kap));
    }
    g = __shfl_sync(0xffffffffu, g, (threadIdx.x & 16), 32);

    const size_t ZOFF = 0;
    const size_t LOFF = (size_t)NN * 128;
    const size_t KOFF = (size_t)NN * 256;

    float* zp = out + ZOFF + (size_t)node * 128 + coff;
    float* lp = out + LOFF + (size_t)node * 128 + coff;
    *(float4*)zp       = make_float4(lbd[0] * g, lbd[1] * g, lbd[2] * g, lbd[3] * g);
    *(float4*)(zp + 4) = make_float4(lbd[4] * g, lbd[5] * g, lbd[6] * g, lbd[7] * g);
    *(float4*)lp       = make_float4(lbd[0], lbd[1], lbd[2], lbd[3]);
    *(float4*)(lp + 4) = make_float4(lbd[4], lbd[5], lbd[6], lbd[7]);
    if (lane == 0) out[KOFF + node] = kap;
}

// ---------------- launch ----------------
extern "C" void kernel_launch(void* const* d_in, const int* in_sizes, int n_in,
                              void* d_out, int out_size) {
    const float* x  = (const float*)d_in[0];
    const int* eidx = (const int*)d_in[1];
    const float* W0 = (const float*)d_in[2];
    const float* W1 = (const float*)d_in[3];
    float* out = (float*)d_out;

    const int4* src4 = (const int4*)eidx;
    const int4* dst4 = (const int4*)(eidx + NE);

    __half* Xh;  cudaGetSymbolAddress((void**)&Xh, d_Xh);
    __half* W0h; cudaGetSymbolAddress((void**)&W0h, d_W0h);
    __half* W1h; cudaGetSymbolAddress((void**)&W1h, d_W1h);
    __half* HAh; cudaGetSymbolAddress((void**)&HAh, d_HAh);
    __half* HB;  cudaGetSymbolAddress((void**)&HB, d_HB);

    // dynamic smem sizes: 3 stages * (A 10240B + B bytes)
    const int smem128 = 3 * (10240 + 32 * (128 + 8) * 2);  // 56832
    const int smem64  = 3 * (10240 + 32 * (64 + 8) * 2);   // 44544
    cudaFuncSetAttribute(k_gemm_cp<128>, cudaFuncAttributeMaxDynamicSharedMemorySize, smem128);
    cudaFuncSetAttribute(k_gemm_cp<64>,  cudaFuncAttributeMaxDynamicSharedMemorySize, smem64);

    // Side stream + events (capture-legal fork/join, proven R6-R9).
    cudaStream_t s1;
    cudaStreamCreateWithFlags(&s1, cudaStreamNonBlocking);
    cudaEvent_t ef, ej;
    cudaEventCreateWithFlags(&ef, cudaEventDisableTiming);
    cudaEventCreateWithFlags(&ej, cudaEventDisableTiming);

    cudaEventRecord(ef, 0);
    cudaStreamWaitEvent(s1, ef, 0);

    // main: x/W0 -> fp16 (submission 0)
    k_cvtx<<<(XCHUNKS + 255) / 256, 256>>>(x, W0);

    // side: CSR part 1 (submissions 1,2)
    k_init<<<(INIT_N + 255) / 256, 256, 0, s1>>>(W1);
    k_hist<<<(NE / 4 + 255) / 256, 256, 0, s1>>>(dst4);

    // main: GEMM1 (submission 3 — ncu capture slot):
    // HAh = Xh @ W0h  (50000x256, K=512), BN=128
    {
        dim3 grid(2, (NN + 127) / 128);
        k_gemm_cp<128><<<grid, 256, smem128>>>(Xh, W0h, HAh, NN, HD1, INDIM,
                                               INDIM, HD1, HD1);
    }

    // side: CSR part 2 (overlaps cvtx+GEMM1)
    k_blocksum<<<NBLK, SCAN_B, 0, s1>>>();
    k_bscan<<<1, 128, 0, s1>>>();
    k_local<<<NBLK, SCAN_B, 0, s1>>>();
    k_fill<<<(NE / 4 + 255) / 256, 256, 0, s1>>>(src4, dst4);
    cudaEventRecord(ej, s1);

    // join: agg1 needs GEMM1 + CSR; GEMM2 needs W1h (also from side)
    cudaStreamWaitEvent(0, ej, 0);

    // AGG1 + softplus -> HB (fp16)
    k_agg1<<<NN / 8, 256>>>();
    // GEMM2: HAh(stride 136) = HB @ W1h  (50000x136, K=256), BN=64
    {
        dim3 grid(3, (NN + 127) / 128);
        k_gemm_cp<64><<<grid, 256, smem64>>>(HB, W1h, HAh, NN, HD2P, HD1,
                                             HD1, HD2P, HD2P);
    }
    // AGG2 + softplus + Weibull epilogue -> out
    k_agg2<<<NN / 16, 256>>>(out);
}